// round 3
// baseline (speedup 1.0000x reference)
#include <cuda_runtime.h>
#include <math.h>

#define NQ    100000
#define NL    32
#define NN    100032
#define QD    384
#define LD    1024
#define H     128
#define EE    1000000
#define ESEE  750000
#define EPRED 250000
#define BN_EPS 1e-5f

// ---------------- scratch (static device globals; no allocation) ------------
__device__ __align__(16) float g_xini[NN * H];   // projected input features
__device__ __align__(16) float g_agg [NN * H];   // scatter target / t / x2
__device__ __align__(16) float g_x1  [NN * H];   // layer-1 output
__device__ int    g_src[ESEE];
__device__ int    g_dst[ESEE];
__device__ __align__(8) float2 g_degew[NN];      // .x = deg, .y = sum(ew)
__device__ float g_colsum[H];
__device__ float g_colsq[H];
__device__ float g_scale[H];
__device__ float g_shift[H];

// ---------------- input projection: x_ini[0:NQ] = q @ Wq + bq ---------------
__global__ void __launch_bounds__(256) proj_q_kernel(const float* __restrict__ A,
                              const float* __restrict__ W,
                              const float* __restrict__ bias) {
    __shared__ __align__(16) float As[64 * 32];
    __shared__ __align__(16) float Ws[32 * 128];
    int tid = threadIdx.x;
    int tx = tid & 15;
    int ty = tid >> 4;
    int row0 = blockIdx.x * 64;

    float acc[4][8];
#pragma unroll
    for (int r = 0; r < 4; r++)
#pragma unroll
        for (int c = 0; c < 8; c++) acc[r][c] = 0.f;

    for (int k0 = 0; k0 < QD; k0 += 32) {
#pragma unroll
        for (int i = 0; i < 2; i++) {
            int idx = tid + i * 256;
            int r = idx >> 3;
            int c4 = idx & 7;
            int grow = row0 + r;
            float4 v = make_float4(0.f, 0.f, 0.f, 0.f);
            if (grow < NQ) v = *(const float4*)&A[(long)grow * QD + k0 + c4 * 4];
            *(float4*)&As[r * 32 + c4 * 4] = v;
        }
#pragma unroll
        for (int i = 0; i < 4; i++) {
            int idx = tid + i * 256;
            int r = idx >> 5;
            int c4 = idx & 31;
            *(float4*)&Ws[r * 128 + c4 * 4] = *(const float4*)&W[(k0 + r) * H + c4 * 4];
        }
        __syncthreads();
#pragma unroll
        for (int k = 0; k < 32; k++) {
            float a[4], b[8];
#pragma unroll
            for (int r = 0; r < 4; r++) a[r] = As[(ty * 4 + r) * 32 + k];
#pragma unroll
            for (int c = 0; c < 8; c++) b[c] = Ws[k * 128 + tx * 8 + c];
#pragma unroll
            for (int r = 0; r < 4; r++)
#pragma unroll
                for (int c = 0; c < 8; c++) acc[r][c] += a[r] * b[c];
        }
        __syncthreads();
    }
#pragma unroll
    for (int r = 0; r < 4; r++) {
        int grow = row0 + ty * 4 + r;
        if (grow < NQ) {
#pragma unroll
            for (int c = 0; c < 8; c += 4) {
                float4 v;
                v.x = acc[r][c + 0] + bias[tx * 8 + c + 0];
                v.y = acc[r][c + 1] + bias[tx * 8 + c + 1];
                v.z = acc[r][c + 2] + bias[tx * 8 + c + 2];
                v.w = acc[r][c + 3] + bias[tx * 8 + c + 3];
                *(float4*)&g_xini[grow * H + tx * 8 + c] = v;
            }
        }
    }
}

// ---------------- llm projection (tiny: 32 rows, K=1024) --------------------
__global__ void proj_l_kernel(const float* __restrict__ A,
                              const float* __restrict__ W,
                              const float* __restrict__ b) {
    int i = blockIdx.x;
    int j = threadIdx.x;
    float acc = b[j];
    for (int k = 0; k < LD; k++) acc += A[i * LD + k] * W[k * H + j];
    g_xini[(NQ + i) * H + j] = acc;
}

// ---------------- edge prep: compact src/dst, deg, sum(ew) ------------------
__global__ void edge_prep_kernel(const int* __restrict__ ei,
                                 const int* __restrict__ ecs,
                                 const float* __restrict__ ewt,
                                 const float* __restrict__ Wem,
                                 const float* __restrict__ bem) {
    int i = blockIdx.x * blockDim.x + threadIdx.x;
    if (i >= ESEE) return;
    int e = ecs[i];
    int s = ei[e];
    int d = ei[EE + e];
    g_src[i] = s;
    g_dst[i] = d;
    float v = ewt[e] * Wem[0] + bem[0];
    v = v > 0.f ? v : 0.01f * v;
    asm volatile("red.global.add.v2.f32 [%0], {%1, %2};"
                 :: "l"(&g_degew[d]), "f"(1.0f), "f"(v) : "memory");
}

// ---------------- scatter-add of 128-float rows with v4 reductions ----------
// One warp per edge: 32 lanes x float4 = 128 floats, 32 red.v4 per edge.
__global__ void __launch_bounds__(256) scatter_kernel(const float* __restrict__ x) {
    int e = blockIdx.x * 8 + (threadIdx.x >> 5);
    int lane = threadIdx.x & 31;
    int s = g_src[e];
    int d = g_dst[e];
    float4 v = *(const float4*)&x[s * H + lane * 4];
    asm volatile("red.global.add.v4.f32 [%0], {%1, %2, %3, %4};"
                 :: "l"(&g_agg[d * H + lane * 4]),
                    "f"(v.x), "f"(v.y), "f"(v.z), "f"(v.w) : "memory");
}

// ---------------- layer GEMM + epilogue + BN column stats -------------------
__global__ void __launch_bounds__(256) layer_gemm_kernel(const float* __restrict__ W,
                                  const float* __restrict__ bm,
                                  const float* __restrict__ be,
                                  const float* __restrict__ We,
                                  const float* __restrict__ xprev) {
    __shared__ __align__(16) float As[64 * 32];
    __shared__ __align__(16) float Ws[32 * 128];
    __shared__ float ps[16 * 128];
    __shared__ float pq[16 * 128];
    int tid = threadIdx.x;
    int tx = tid & 15;
    int ty = tid >> 4;
    int row0 = blockIdx.x * 64;

    float acc[4][8];
#pragma unroll
    for (int r = 0; r < 4; r++)
#pragma unroll
        for (int c = 0; c < 8; c++) acc[r][c] = 0.f;

    for (int k0 = 0; k0 < H; k0 += 32) {
#pragma unroll
        for (int i = 0; i < 2; i++) {
            int idx = tid + i * 256;
            int r = idx >> 3;
            int c4 = idx & 7;
            *(float4*)&As[r * 32 + c4 * 4] =
                *(const float4*)&g_agg[(row0 + r) * H + k0 + c4 * 4];
        }
#pragma unroll
        for (int i = 0; i < 4; i++) {
            int idx = tid + i * 256;
            int r = idx >> 5;
            int c4 = idx & 31;
            *(float4*)&Ws[r * 128 + c4 * 4] = *(const float4*)&W[(k0 + r) * H + c4 * 4];
        }
        __syncthreads();
#pragma unroll
        for (int k = 0; k < 32; k++) {
            float a[4], b[8];
#pragma unroll
            for (int r = 0; r < 4; r++) a[r] = As[(ty * 4 + r) * 32 + k];
#pragma unroll
            for (int c = 0; c < 8; c++) b[c] = Ws[k * 128 + tx * 8 + c];
#pragma unroll
            for (int r = 0; r < 4; r++)
#pragma unroll
                for (int c = 0; c < 8; c++) acc[r][c] += a[r] * b[c];
        }
        __syncthreads();
    }

    int col0 = tx * 8;
    float cb[8], we[8];
#pragma unroll
    for (int c = 0; c < 8; c++) {
        cb[c] = bm[col0 + c] + be[col0 + c];
        we[c] = We[col0 + c];
    }
    float lsum[8], lsq[8];
#pragma unroll
    for (int c = 0; c < 8; c++) { lsum[c] = 0.f; lsq[c] = 0.f; }

#pragma unroll
    for (int r = 0; r < 4; r++) {
        int grow = row0 + ty * 4 + r;
        float2 ds = g_degew[grow];
#pragma unroll
        for (int c = 0; c < 8; c++) {
            float t = acc[r][c] + ds.x * cb[c] + ds.y * we[c] + xprev[grow * H + col0 + c];
            acc[r][c] = t;
            lsum[c] += t;
            lsq[c] += t * t;
        }
#pragma unroll
        for (int c = 0; c < 8; c += 4) {
            float4 v;
            v.x = acc[r][c + 0]; v.y = acc[r][c + 1];
            v.z = acc[r][c + 2]; v.w = acc[r][c + 3];
            *(float4*)&g_agg[grow * H + col0 + c] = v;
        }
    }
#pragma unroll
    for (int c = 0; c < 8; c++) {
        ps[ty * 128 + col0 + c] = lsum[c];
        pq[ty * 128 + col0 + c] = lsq[c];
    }
    __syncthreads();
    if (tid < 128) {
        float s = 0.f, q = 0.f;
#pragma unroll
        for (int y = 0; y < 16; y++) {
            s += ps[y * 128 + tid];
            q += pq[y * 128 + tid];
        }
        atomicAdd(&g_colsum[tid], s);
        atomicAdd(&g_colsq[tid], q);
    }
}

// ---------------- BN stat finalize -> affine scale/shift --------------------
__global__ void finalize_kernel(const float* __restrict__ g,
                                const float* __restrict__ beta) {
    int j = threadIdx.x;
    float mu = g_colsum[j] * (1.f / (float)NN);
    float var = g_colsq[j] * (1.f / (float)NN) - mu * mu;
    float rstd = rsqrtf(var + BN_EPS);
    float sc = g[j] * rstd;
    g_scale[j] = sc;
    g_shift[j] = beta[j] - mu * sc;
}

// ---------------- BN apply (+ optional leaky relu) ---------------------------
__global__ void apply_kernel(const float* __restrict__ in,
                             float* __restrict__ out, int do_lrelu) {
    int i = blockIdx.x * blockDim.x + threadIdx.x;
    int c = (i * 4) & 127;
    float4 v = *(const float4*)&in[i * 4];
    v.x = v.x * g_scale[c + 0] + g_shift[c + 0];
    v.y = v.y * g_scale[c + 1] + g_shift[c + 1];
    v.z = v.z * g_scale[c + 2] + g_shift[c + 2];
    v.w = v.w * g_scale[c + 3] + g_shift[c + 3];
    if (do_lrelu) {
        v.x = v.x > 0.f ? v.x : 0.01f * v.x;
        v.y = v.y > 0.f ? v.y : 0.01f * v.y;
        v.z = v.z > 0.f ? v.z : 0.01f * v.z;
        v.w = v.w > 0.f ? v.w : 0.01f * v.w;
    }
    *(float4*)&out[i * 4] = v;
}

// ---------------- edge prediction --------------------------------------------
__global__ void predict_kernel(const int* __restrict__ ei,
                               const int* __restrict__ em,
                               const float* __restrict__ x2,
                               float* __restrict__ out) {
    int warp = (blockIdx.x * blockDim.x + threadIdx.x) >> 5;
    int lane = threadIdx.x & 31;
    if (warp >= EPRED) return;
    int e = em[warp];
    int s = ei[e];
    int t = ei[EE + e];
    float4 a = *(const float4*)&g_xini[s * H + lane * 4];
    float4 b = *(const float4*)&x2[t * H + lane * 4];
    float d = a.x * b.x + a.y * b.y + a.z * b.z + a.w * b.w;
#pragma unroll
    for (int o = 16; o; o >>= 1) d += __shfl_xor_sync(0xffffffffu, d, o);
    if (lane == 0) out[warp] = 1.f / (1.f + expf(-d * (1.f / 128.f)));
}

// ---------------- launch -----------------------------------------------------
extern "C" void kernel_launch(void* const* d_in, const int* in_sizes, int n_in,
                              void* d_out, int out_size) {
    const float* qf  = (const float*)d_in[0];
    const float* lf  = (const float*)d_in[1];
    const int*   ei  = (const int*)d_in[2];
    const int*   em  = (const int*)d_in[3];
    const int*   ecs = (const int*)d_in[4];
    const float* ewt = (const float*)d_in[5];
    const float* Wq  = (const float*)d_in[6];
    const float* bq  = (const float*)d_in[7];
    const float* Wl  = (const float*)d_in[8];
    const float* bl  = (const float*)d_in[9];
    const float* Wem = (const float*)d_in[10];
    const float* bem = (const float*)d_in[11];
    const float* W1m = (const float*)d_in[12];
    const float* b1m = (const float*)d_in[13];
    const float* W1e = (const float*)d_in[14];
    const float* b1e = (const float*)d_in[15];
    const float* W2m = (const float*)d_in[16];
    const float* b2m = (const float*)d_in[17];
    const float* W2e = (const float*)d_in[18];
    const float* b2e = (const float*)d_in[19];
    const float* g1    = (const float*)d_in[20];
    const float* beta1 = (const float*)d_in[21];
    const float* g2    = (const float*)d_in[22];
    const float* beta2 = (const float*)d_in[23];
    float* out = (float*)d_out;

    void *p_agg, *p_xini, *p_x1, *p_degew, *p_colsum, *p_colsq;
    cudaGetSymbolAddress(&p_agg, g_agg);
    cudaGetSymbolAddress(&p_xini, g_xini);
    cudaGetSymbolAddress(&p_x1, g_x1);
    cudaGetSymbolAddress(&p_degew, g_degew);
    cudaGetSymbolAddress(&p_colsum, g_colsum);
    cudaGetSymbolAddress(&p_colsq, g_colsq);

    cudaMemsetAsync(p_degew, 0, NN * sizeof(float2));

    // input projections
    proj_q_kernel<<<NN / 64, 256>>>(qf, Wq, bq);
    proj_l_kernel<<<NL, H>>>(lf, Wl, bl);

    // edge preprocessing
    edge_prep_kernel<<<(ESEE + 255) / 256, 256>>>(ei, ecs, ewt, Wem, bem);

    // ---- layer 1 ----
    cudaMemsetAsync(p_agg, 0, (size_t)NN * H * sizeof(float));
    scatter_kernel<<<ESEE / 8, 256>>>((const float*)p_xini);
    cudaMemsetAsync(p_colsum, 0, H * sizeof(float));
    cudaMemsetAsync(p_colsq, 0, H * sizeof(float));
    layer_gemm_kernel<<<NN / 64, 256>>>(W1m, b1m, b1e, W1e, (const float*)p_xini);
    finalize_kernel<<<1, H>>>(g1, beta1);
    apply_kernel<<<(NN * H / 4) / 256, 256>>>((const float*)p_agg, (float*)p_x1, 1);

    // ---- layer 2 ----
    cudaMemsetAsync(p_agg, 0, (size_t)NN * H * sizeof(float));
    scatter_kernel<<<ESEE / 8, 256>>>((const float*)p_x1);
    cudaMemsetAsync(p_colsum, 0, H * sizeof(float));
    cudaMemsetAsync(p_colsq, 0, H * sizeof(float));
    layer_gemm_kernel<<<NN / 64, 256>>>(W2m, b2m, b2e, W2e, (const float*)p_x1);
    finalize_kernel<<<1, H>>>(g2, beta2);
    apply_kernel<<<(NN * H / 4) / 256, 256>>>((const float*)p_agg, (float*)p_agg, 0);

    // ---- edge prediction ----
    predict_kernel<<<EPRED / 8, 256>>>(ei, em, (const float*)p_agg, out);
}

// round 4
// speedup vs baseline: 1.3859x; 1.3859x over previous
#include <cuda_runtime.h>
#include <math.h>

#define NQ    100000
#define NL    32
#define NN    100032
#define QD    384
#define LD    1024
#define H     128
#define EE    1000000
#define ESEE  750000
#define EPRED 250000
#define BN_EPS 1e-5f
#define ASTRIDE 36   // padded A-tile row stride (floats): conflict-free STS/LDS

// ---------------- scratch (static device globals; no allocation) ------------
__device__ __align__(16) float g_xini[NN * H];
__device__ __align__(16) float g_agg [NN * H];
__device__ __align__(16) float g_x1  [NN * H];
__device__ int    g_src[ESEE];
__device__ int    g_dst[ESEE];
__device__ __align__(8) float2 g_degew[NN];
__device__ float g_colsum[H];
__device__ float g_colsq[H];
__device__ float g_scale[H];
__device__ float g_shift[H];

// ---------------- input projection: x_ini[0:NQ] = q @ Wq + bq ---------------
__global__ void __launch_bounds__(256) proj_q_kernel(const float* __restrict__ A,
                              const float* __restrict__ W,
                              const float* __restrict__ bias) {
    __shared__ __align__(16) float As[64 * ASTRIDE];
    __shared__ __align__(16) float Ws[32 * 128];
    int tid = threadIdx.x;
    int tx = tid & 15;
    int ty = tid >> 4;
    int row0 = blockIdx.x * 64;

    float acc[4][8];
#pragma unroll
    for (int r = 0; r < 4; r++)
#pragma unroll
        for (int c = 0; c < 8; c++) acc[r][c] = 0.f;

    for (int k0 = 0; k0 < QD; k0 += 32) {
#pragma unroll
        for (int i = 0; i < 2; i++) {
            int idx = tid + i * 256;
            int r = idx >> 3;
            int c4 = idx & 7;
            int grow = row0 + r;
            float4 v = make_float4(0.f, 0.f, 0.f, 0.f);
            if (grow < NQ) v = *(const float4*)&A[(long)grow * QD + k0 + c4 * 4];
            *(float4*)&As[r * ASTRIDE + c4 * 4] = v;
        }
#pragma unroll
        for (int i = 0; i < 4; i++) {
            int idx = tid + i * 256;
            int r = idx >> 5;
            int c4 = idx & 31;
            *(float4*)&Ws[r * 128 + c4 * 4] = *(const float4*)&W[(k0 + r) * H + c4 * 4];
        }
        __syncthreads();
#pragma unroll
        for (int k = 0; k < 32; k++) {
            float a0 = As[(ty * 4 + 0) * ASTRIDE + k];
            float a1 = As[(ty * 4 + 1) * ASTRIDE + k];
            float a2 = As[(ty * 4 + 2) * ASTRIDE + k];
            float a3 = As[(ty * 4 + 3) * ASTRIDE + k];
            float4 b0 = *(const float4*)&Ws[k * 128 + tx * 8];
            float4 b1 = *(const float4*)&Ws[k * 128 + tx * 8 + 4];
            float b[8] = {b0.x, b0.y, b0.z, b0.w, b1.x, b1.y, b1.z, b1.w};
            float a[4] = {a0, a1, a2, a3};
#pragma unroll
            for (int r = 0; r < 4; r++)
#pragma unroll
                for (int c = 0; c < 8; c++) acc[r][c] += a[r] * b[c];
        }
        __syncthreads();
    }
#pragma unroll
    for (int r = 0; r < 4; r++) {
        int grow = row0 + ty * 4 + r;
        if (grow < NQ) {
#pragma unroll
            for (int c = 0; c < 8; c += 4) {
                float4 v;
                v.x = acc[r][c + 0] + bias[tx * 8 + c + 0];
                v.y = acc[r][c + 1] + bias[tx * 8 + c + 1];
                v.z = acc[r][c + 2] + bias[tx * 8 + c + 2];
                v.w = acc[r][c + 3] + bias[tx * 8 + c + 3];
                *(float4*)&g_xini[grow * H + tx * 8 + c] = v;
            }
        }
    }
}

// ---------------- llm projection (tiny: 32 rows, K=1024) --------------------
__global__ void proj_l_kernel(const float* __restrict__ A,
                              const float* __restrict__ W,
                              const float* __restrict__ b) {
    int i = blockIdx.x;
    int j = threadIdx.x;
    float acc = b[j];
    for (int k = 0; k < LD; k++) acc += A[i * LD + k] * W[k * H + j];
    g_xini[(NQ + i) * H + j] = acc;
}

// ---------------- edge prep: compact src/dst, deg, sum(ew) ------------------
__global__ void edge_prep_kernel(const int* __restrict__ ei,
                                 const int* __restrict__ ecs,
                                 const float* __restrict__ ewt,
                                 const float* __restrict__ Wem,
                                 const float* __restrict__ bem) {
    int i = blockIdx.x * blockDim.x + threadIdx.x;
    if (i >= ESEE) return;
    int e = ecs[i];
    int s = ei[e];
    int d = ei[EE + e];
    g_src[i] = s;
    g_dst[i] = d;
    float v = ewt[e] * Wem[0] + bem[0];
    v = v > 0.f ? v : 0.01f * v;
    asm volatile("red.global.add.v2.f32 [%0], {%1, %2};"
                 :: "l"(&g_degew[d]), "f"(1.0f), "f"(v) : "memory");
}

// ---------------- scatter-add of 128-float rows with v4 reductions ----------
__global__ void __launch_bounds__(256) scatter_kernel(const float* __restrict__ x) {
    int e = blockIdx.x * 8 + (threadIdx.x >> 5);
    int lane = threadIdx.x & 31;
    int s = g_src[e];
    int d = g_dst[e];
    float4 v = *(const float4*)&x[s * H + lane * 4];
    asm volatile("red.global.add.v4.f32 [%0], {%1, %2, %3, %4};"
                 :: "l"(&g_agg[d * H + lane * 4]),
                    "f"(v.x), "f"(v.y), "f"(v.z), "f"(v.w) : "memory");
}

// ---------------- layer GEMM + epilogue + BN column stats -------------------
__global__ void __launch_bounds__(256) layer_gemm_kernel(const float* __restrict__ W,
                                  const float* __restrict__ bm,
                                  const float* __restrict__ be,
                                  const float* __restrict__ We,
                                  const float* __restrict__ xprev) {
    __shared__ __align__(16) float As[64 * ASTRIDE];
    __shared__ __align__(16) float Ws[32 * 128];
    __shared__ float ps[16 * 128];
    __shared__ float pq[16 * 128];
    int tid = threadIdx.x;
    int tx = tid & 15;
    int ty = tid >> 4;
    int row0 = blockIdx.x * 64;

    float acc[4][8];
#pragma unroll
    for (int r = 0; r < 4; r++)
#pragma unroll
        for (int c = 0; c < 8; c++) acc[r][c] = 0.f;

    for (int k0 = 0; k0 < H; k0 += 32) {
#pragma unroll
        for (int i = 0; i < 2; i++) {
            int idx = tid + i * 256;
            int r = idx >> 3;
            int c4 = idx & 7;
            *(float4*)&As[r * ASTRIDE + c4 * 4] =
                *(const float4*)&g_agg[(row0 + r) * H + k0 + c4 * 4];
        }
#pragma unroll
        for (int i = 0; i < 4; i++) {
            int idx = tid + i * 256;
            int r = idx >> 5;
            int c4 = idx & 31;
            *(float4*)&Ws[r * 128 + c4 * 4] = *(const float4*)&W[(k0 + r) * H + c4 * 4];
        }
        __syncthreads();
#pragma unroll
        for (int k = 0; k < 32; k++) {
            float a0 = As[(ty * 4 + 0) * ASTRIDE + k];
            float a1 = As[(ty * 4 + 1) * ASTRIDE + k];
            float a2 = As[(ty * 4 + 2) * ASTRIDE + k];
            float a3 = As[(ty * 4 + 3) * ASTRIDE + k];
            float4 b0 = *(const float4*)&Ws[k * 128 + tx * 8];
            float4 b1 = *(const float4*)&Ws[k * 128 + tx * 8 + 4];
            float b[8] = {b0.x, b0.y, b0.z, b0.w, b1.x, b1.y, b1.z, b1.w};
            float a[4] = {a0, a1, a2, a3};
#pragma unroll
            for (int r = 0; r < 4; r++)
#pragma unroll
                for (int c = 0; c < 8; c++) acc[r][c] += a[r] * b[c];
        }
        __syncthreads();
    }

    int col0 = tx * 8;
    float cb[8], we[8];
#pragma unroll
    for (int c = 0; c < 8; c++) {
        cb[c] = bm[col0 + c] + be[col0 + c];
        we[c] = We[col0 + c];
    }
    float lsum[8], lsq[8];
#pragma unroll
    for (int c = 0; c < 8; c++) { lsum[c] = 0.f; lsq[c] = 0.f; }

#pragma unroll
    for (int r = 0; r < 4; r++) {
        int grow = row0 + ty * 4 + r;
        float2 ds = g_degew[grow];
#pragma unroll
        for (int c = 0; c < 8; c++) {
            float t = acc[r][c] + ds.x * cb[c] + ds.y * we[c] + xprev[grow * H + col0 + c];
            acc[r][c] = t;
            lsum[c] += t;
            lsq[c] += t * t;
        }
#pragma unroll
        for (int c = 0; c < 8; c += 4) {
            float4 v;
            v.x = acc[r][c + 0]; v.y = acc[r][c + 1];
            v.z = acc[r][c + 2]; v.w = acc[r][c + 3];
            *(float4*)&g_agg[grow * H + col0 + c] = v;
        }
    }
#pragma unroll
    for (int c = 0; c < 8; c++) {
        ps[ty * 128 + col0 + c] = lsum[c];
        pq[ty * 128 + col0 + c] = lsq[c];
    }
    __syncthreads();
    if (tid < 128) {
        float s = 0.f, q = 0.f;
#pragma unroll
        for (int y = 0; y < 16; y++) {
            s += ps[y * 128 + tid];
            q += pq[y * 128 + tid];
        }
        atomicAdd(&g_colsum[tid], s);
        atomicAdd(&g_colsq[tid], q);
    }
}

// ---------------- BN stat finalize -> affine scale/shift --------------------
__global__ void finalize_kernel(const float* __restrict__ g,
                                const float* __restrict__ beta) {
    int j = threadIdx.x;
    float mu = g_colsum[j] * (1.f / (float)NN);
    float var = g_colsq[j] * (1.f / (float)NN) - mu * mu;
    float rstd = rsqrtf(var + BN_EPS);
    float sc = g[j] * rstd;
    g_scale[j] = sc;
    g_shift[j] = beta[j] - mu * sc;
}

// ---------------- BN apply (+ optional leaky relu) ---------------------------
__global__ void apply_kernel(const float* __restrict__ in,
                             float* __restrict__ out, int do_lrelu) {
    int i = blockIdx.x * blockDim.x + threadIdx.x;
    int c = (i * 4) & 127;
    float4 v = *(const float4*)&in[i * 4];
    v.x = v.x * g_scale[c + 0] + g_shift[c + 0];
    v.y = v.y * g_scale[c + 1] + g_shift[c + 1];
    v.z = v.z * g_scale[c + 2] + g_shift[c + 2];
    v.w = v.w * g_scale[c + 3] + g_shift[c + 3];
    if (do_lrelu) {
        v.x = v.x > 0.f ? v.x : 0.01f * v.x;
        v.y = v.y > 0.f ? v.y : 0.01f * v.y;
        v.z = v.z > 0.f ? v.z : 0.01f * v.z;
        v.w = v.w > 0.f ? v.w : 0.01f * v.w;
    }
    *(float4*)&out[i * 4] = v;
}

// ---------------- edge prediction --------------------------------------------
__global__ void predict_kernel(const int* __restrict__ ei,
                               const int* __restrict__ em,
                               const float* __restrict__ x2,
                               float* __restrict__ out) {
    int warp = (blockIdx.x * blockDim.x + threadIdx.x) >> 5;
    int lane = threadIdx.x & 31;
    if (warp >= EPRED) return;
    int e = em[warp];
    int s = ei[e];
    int t = ei[EE + e];
    float4 a = *(const float4*)&g_xini[s * H + lane * 4];
    float4 b = *(const float4*)&x2[t * H + lane * 4];
    float d = a.x * b.x + a.y * b.y + a.z * b.z + a.w * b.w;
#pragma unroll
    for (int o = 16; o; o >>= 1) d += __shfl_xor_sync(0xffffffffu, d, o);
    if (lane == 0) out[warp] = 1.f / (1.f + expf(-d * (1.f / 128.f)));
}

// ---------------- launch -----------------------------------------------------
extern "C" void kernel_launch(void* const* d_in, const int* in_sizes, int n_in,
                              void* d_out, int out_size) {
    const float* qf  = (const float*)d_in[0];
    const float* lf  = (const float*)d_in[1];
    const int*   ei  = (const int*)d_in[2];
    const int*   em  = (const int*)d_in[3];
    const int*   ecs = (const int*)d_in[4];
    const float* ewt = (const float*)d_in[5];
    const float* Wq  = (const float*)d_in[6];
    const float* bq  = (const float*)d_in[7];
    const float* Wl  = (const float*)d_in[8];
    const float* bl  = (const float*)d_in[9];
    const float* Wem = (const float*)d_in[10];
    const float* bem = (const float*)d_in[11];
    const float* W1m = (const float*)d_in[12];
    const float* b1m = (const float*)d_in[13];
    const float* W1e = (const float*)d_in[14];
    const float* b1e = (const float*)d_in[15];
    const float* W2m = (const float*)d_in[16];
    const float* b2m = (const float*)d_in[17];
    const float* W2e = (const float*)d_in[18];
    const float* b2e = (const float*)d_in[19];
    const float* g1    = (const float*)d_in[20];
    const float* beta1 = (const float*)d_in[21];
    const float* g2    = (const float*)d_in[22];
    const float* beta2 = (const float*)d_in[23];
    float* out = (float*)d_out;

    void *p_agg, *p_xini, *p_x1, *p_degew, *p_colsum, *p_colsq;
    cudaGetSymbolAddress(&p_agg, g_agg);
    cudaGetSymbolAddress(&p_xini, g_xini);
    cudaGetSymbolAddress(&p_x1, g_x1);
    cudaGetSymbolAddress(&p_degew, g_degew);
    cudaGetSymbolAddress(&p_colsum, g_colsum);
    cudaGetSymbolAddress(&p_colsq, g_colsq);

    cudaMemsetAsync(p_degew, 0, NN * sizeof(float2));

    // input projections
    proj_q_kernel<<<NN / 64, 256>>>(qf, Wq, bq);
    proj_l_kernel<<<NL, H>>>(lf, Wl, bl);

    // edge preprocessing
    edge_prep_kernel<<<(ESEE + 255) / 256, 256>>>(ei, ecs, ewt, Wem, bem);

    // ---- layer 1 ----
    cudaMemsetAsync(p_agg, 0, (size_t)NN * H * sizeof(float));
    scatter_kernel<<<ESEE / 8, 256>>>((const float*)p_xini);
    cudaMemsetAsync(p_colsum, 0, H * sizeof(float));
    cudaMemsetAsync(p_colsq, 0, H * sizeof(float));
    layer_gemm_kernel<<<NN / 64, 256>>>(W1m, b1m, b1e, W1e, (const float*)p_xini);
    finalize_kernel<<<1, H>>>(g1, beta1);
    apply_kernel<<<(NN * H / 4) / 256, 256>>>((const float*)p_agg, (float*)p_x1, 1);

    // ---- layer 2 ----
    cudaMemsetAsync(p_agg, 0, (size_t)NN * H * sizeof(float));
    scatter_kernel<<<ESEE / 8, 256>>>((const float*)p_x1);
    cudaMemsetAsync(p_colsum, 0, H * sizeof(float));
    cudaMemsetAsync(p_colsq, 0, H * sizeof(float));
    layer_gemm_kernel<<<NN / 64, 256>>>(W2m, b2m, b2e, W2e, (const float*)p_x1);
    finalize_kernel<<<1, H>>>(g2, beta2);
    apply_kernel<<<(NN * H / 4) / 256, 256>>>((const float*)p_agg, (float*)p_agg, 0);

    // ---- edge prediction ----
    predict_kernel<<<EPRED / 8, 256>>>(ei, em, (const float*)p_agg, out);
}

// round 5
// speedup vs baseline: 1.6667x; 1.2026x over previous
#include <cuda_runtime.h>
#include <math.h>

#define NQ    100000
#define NL    32
#define NN    100032
#define QD    384
#define LD    1024
#define H     128
#define EE    1000000
#define ESEE  750000
#define EPRED 250000
#define BN_EPS 1e-5f
#define APAD  20   // padded A-tile row stride (floats) for BK=16

// ---------------- scratch (static device globals; no allocation) ------------
__device__ __align__(16) float g_xini[NN * H];
__device__ __align__(16) float g_agg [NN * H];   // scatter1 target / t1 (raw layer-1 out)
__device__ __align__(16) float g_x1  [NN * H];   // scatter2 target / t2 (raw layer-2 out)
__device__ int    g_src[ESEE];
__device__ int    g_dst[ESEE];
__device__ __align__(8) float2 g_degew[NN];
__device__ float g_colstats[2 * H];              // [0:128) sum, [128:256) sumsq
__device__ float g_scale1[H], g_shift1[H];
__device__ float g_scale2[H], g_shift2[H];

// ---------------- cp.async helpers ------------------------------------------
__device__ __forceinline__ unsigned smem_u32(const void* p) {
    return (unsigned)__cvta_generic_to_shared(p);
}
__device__ __forceinline__ void cp16(unsigned dst, const void* src) {
    asm volatile("cp.async.ca.shared.global [%0], [%1], 16;" :: "r"(dst), "l"(src));
}
__device__ __forceinline__ void cp16z(unsigned dst, const void* src, unsigned sz) {
    asm volatile("cp.async.ca.shared.global [%0], [%1], 16, %2;"
                 :: "r"(dst), "l"(src), "r"(sz));
}
#define CP_COMMIT() asm volatile("cp.async.commit_group;")

// ---------------- input projection: x_ini[0:NQ] = q @ Wq + bq ---------------
// 64x128 tile, BK=16, 2-stage cp.async pipeline, 256 thr, 4x8 per thread.
__global__ void __launch_bounds__(256) proj_q_kernel(const float* __restrict__ A,
                              const float* __restrict__ W,
                              const float* __restrict__ bias) {
    __shared__ __align__(16) float As[2][64 * APAD];
    __shared__ __align__(16) float Ws[2][16 * 128];
    int tid = threadIdx.x;
    int tx = tid & 15;
    int ty = tid >> 4;
    int row0 = blockIdx.x * 64;

    int ar = tid >> 2, ac = (tid & 3) * 4;     // A loader: 1 float4/thread
    int wr = tid >> 5, wc = (tid & 31) * 4;    // W loader: 2 float4/thread
    int garow = row0 + ar;
    unsigned asz = (garow < NQ) ? 16u : 0u;
    const float* aptr = A + (long)garow * QD + ac;

    float acc[4][8];
#pragma unroll
    for (int r = 0; r < 4; r++)
#pragma unroll
        for (int c = 0; c < 8; c++) acc[r][c] = 0.f;

    // prologue: stage 0
    cp16z(smem_u32(&As[0][ar * APAD + ac]), aptr, asz);
    cp16(smem_u32(&Ws[0][wr * 128 + wc]), &W[wr * H + wc]);
    cp16(smem_u32(&Ws[0][(wr + 8) * 128 + wc]), &W[(wr + 8) * H + wc]);
    CP_COMMIT();

    const int T = QD / 16;  // 24
    for (int t = 0; t < T; t++) {
        int buf = t & 1;
        if (t + 1 < T) {
            int nb = buf ^ 1;
            int k0 = (t + 1) * 16;
            cp16z(smem_u32(&As[nb][ar * APAD + ac]), aptr + k0, asz);
            cp16(smem_u32(&Ws[nb][wr * 128 + wc]), &W[(k0 + wr) * H + wc]);
            cp16(smem_u32(&Ws[nb][(k0 ? (wr + 8) : (wr + 8)) * 128 + wc]),
                 &W[(k0 + wr + 8) * H + wc]);
            CP_COMMIT();
            asm volatile("cp.async.wait_group 1;");
        } else {
            asm volatile("cp.async.wait_group 0;");
        }
        __syncthreads();
#pragma unroll
        for (int k = 0; k < 16; k++) {
            float a[4];
#pragma unroll
            for (int r = 0; r < 4; r++) a[r] = As[buf][(ty * 4 + r) * APAD + k];
            float4 b0 = *(const float4*)&Ws[buf][k * 128 + tx * 8];
            float4 b1 = *(const float4*)&Ws[buf][k * 128 + tx * 8 + 4];
            float b[8] = {b0.x, b0.y, b0.z, b0.w, b1.x, b1.y, b1.z, b1.w};
#pragma unroll
            for (int r = 0; r < 4; r++)
#pragma unroll
                for (int c = 0; c < 8; c++) acc[r][c] += a[r] * b[c];
        }
        __syncthreads();
    }
#pragma unroll
    for (int r = 0; r < 4; r++) {
        int grow = row0 + ty * 4 + r;
        if (grow < NQ) {
#pragma unroll
            for (int c = 0; c < 8; c += 4) {
                float4 v;
                v.x = acc[r][c + 0] + bias[tx * 8 + c + 0];
                v.y = acc[r][c + 1] + bias[tx * 8 + c + 1];
                v.z = acc[r][c + 2] + bias[tx * 8 + c + 2];
                v.w = acc[r][c + 3] + bias[tx * 8 + c + 3];
                *(float4*)&g_xini[grow * H + tx * 8 + c] = v;
            }
        }
    }
}

// ---------------- llm projection (tiny: 32 rows, K=1024) --------------------
__global__ void proj_l_kernel(const float* __restrict__ A,
                              const float* __restrict__ W,
                              const float* __restrict__ b) {
    int i = blockIdx.x;
    int j = threadIdx.x;
    float acc = b[j];
    for (int k = 0; k < LD; k++) acc += A[i * LD + k] * W[k * H + j];
    g_xini[(NQ + i) * H + j] = acc;
}

// ---------------- edge prep: compact src/dst, deg, sum(ew) ------------------
__global__ void edge_prep_kernel(const int* __restrict__ ei,
                                 const int* __restrict__ ecs,
                                 const float* __restrict__ ewt,
                                 const float* __restrict__ Wem,
                                 const float* __restrict__ bem) {
    int i = blockIdx.x * blockDim.x + threadIdx.x;
    if (i >= ESEE) return;
    int e = ecs[i];
    int s = ei[e];
    int d = ei[EE + e];
    g_src[i] = s;
    g_dst[i] = d;
    float v = ewt[e] * Wem[0] + bem[0];
    v = v > 0.f ? v : 0.01f * v;
    asm volatile("red.global.add.v2.f32 [%0], {%1, %2};"
                 :: "l"(&g_degew[d]), "f"(1.0f), "f"(v) : "memory");
}

// ---------------- scatter-add (raw rows) -------------------------------------
__global__ void __launch_bounds__(256) scatter_raw_kernel(const float* __restrict__ x,
                                                          float* __restrict__ outbuf) {
    int e = blockIdx.x * 8 + (threadIdx.x >> 5);
    int lane = threadIdx.x & 31;
    int s = g_src[e];
    int d = g_dst[e];
    float4 v = *(const float4*)&x[s * H + lane * 4];
    asm volatile("red.global.add.v4.f32 [%0], {%1, %2, %3, %4};"
                 :: "l"(&outbuf[d * H + lane * 4]),
                    "f"(v.x), "f"(v.y), "f"(v.z), "f"(v.w) : "memory");
}

// ---------------- scatter-add with inline BN + leaky relu --------------------
__global__ void __launch_bounds__(256) scatter_bn_kernel(const float* __restrict__ x,
                                                         float* __restrict__ outbuf,
                                                         const float* __restrict__ sc,
                                                         const float* __restrict__ sh) {
    int e = blockIdx.x * 8 + (threadIdx.x >> 5);
    int lane = threadIdx.x & 31;
    float4 s4 = *(const float4*)&sc[lane * 4];
    float4 h4 = *(const float4*)&sh[lane * 4];
    int s = g_src[e];
    int d = g_dst[e];
    float4 v = *(const float4*)&x[s * H + lane * 4];
    v.x = fmaf(v.x, s4.x, h4.x); v.x = v.x > 0.f ? v.x : 0.01f * v.x;
    v.y = fmaf(v.y, s4.y, h4.y); v.y = v.y > 0.f ? v.y : 0.01f * v.y;
    v.z = fmaf(v.z, s4.z, h4.z); v.z = v.z > 0.f ? v.z : 0.01f * v.z;
    v.w = fmaf(v.w, s4.w, h4.w); v.w = v.w > 0.f ? v.w : 0.01f * v.w;
    asm volatile("red.global.add.v4.f32 [%0], {%1, %2, %3, %4};"
                 :: "l"(&outbuf[d * H + lane * 4]),
                    "f"(v.x), "f"(v.y), "f"(v.z), "f"(v.w) : "memory");
}

// ---------------- layer GEMM + epilogue + BN column stats -------------------
// out = Ain @ W + deg*(bm+be) + sumew*We + f(xprev), f = identity or bn1+lrelu
__global__ void __launch_bounds__(256) layer_gemm_kernel(const float* __restrict__ Ain,
                                  const float* __restrict__ W,
                                  const float* __restrict__ bm,
                                  const float* __restrict__ be,
                                  const float* __restrict__ We,
                                  const float* __restrict__ xprev,
                                  const float* __restrict__ psc,
                                  const float* __restrict__ psh,
                                  int prev_bn,
                                  float* __restrict__ out) {
    __shared__ __align__(16) float As[2][64 * APAD];
    __shared__ __align__(16) float Ws[2][16 * 128];
    __shared__ float ps[16 * 128];
    __shared__ float pq[16 * 128];
    int tid = threadIdx.x;
    int tx = tid & 15;
    int ty = tid >> 4;
    int row0 = blockIdx.x * 64;

    int ar = tid >> 2, ac = (tid & 3) * 4;
    int wr = tid >> 5, wc = (tid & 31) * 4;
    const float* aptr = Ain + (long)(row0 + ar) * H + ac;

    float acc[4][8];
#pragma unroll
    for (int r = 0; r < 4; r++)
#pragma unroll
        for (int c = 0; c < 8; c++) acc[r][c] = 0.f;

    cp16(smem_u32(&As[0][ar * APAD + ac]), aptr);
    cp16(smem_u32(&Ws[0][wr * 128 + wc]), &W[wr * H + wc]);
    cp16(smem_u32(&Ws[0][(wr + 8) * 128 + wc]), &W[(wr + 8) * H + wc]);
    CP_COMMIT();

    const int T = H / 16;  // 8
    for (int t = 0; t < T; t++) {
        int buf = t & 1;
        if (t + 1 < T) {
            int nb = buf ^ 1;
            int k0 = (t + 1) * 16;
            cp16(smem_u32(&As[nb][ar * APAD + ac]), aptr + k0);
            cp16(smem_u32(&Ws[nb][wr * 128 + wc]), &W[(k0 + wr) * H + wc]);
            cp16(smem_u32(&Ws[nb][(wr + 8) * 128 + wc]), &W[(k0 + wr + 8) * H + wc]);
            CP_COMMIT();
            asm volatile("cp.async.wait_group 1;");
        } else {
            asm volatile("cp.async.wait_group 0;");
        }
        __syncthreads();
#pragma unroll
        for (int k = 0; k < 16; k++) {
            float a[4];
#pragma unroll
            for (int r = 0; r < 4; r++) a[r] = As[buf][(ty * 4 + r) * APAD + k];
            float4 b0 = *(const float4*)&Ws[buf][k * 128 + tx * 8];
            float4 b1 = *(const float4*)&Ws[buf][k * 128 + tx * 8 + 4];
            float b[8] = {b0.x, b0.y, b0.z, b0.w, b1.x, b1.y, b1.z, b1.w};
#pragma unroll
            for (int r = 0; r < 4; r++)
#pragma unroll
                for (int c = 0; c < 8; c++) acc[r][c] += a[r] * b[c];
        }
        __syncthreads();
    }

    int col0 = tx * 8;
    float cb[8], wev[8], sc1[8], sh1[8];
#pragma unroll
    for (int c = 0; c < 8; c++) {
        cb[c]  = bm[col0 + c] + be[col0 + c];
        wev[c] = We[col0 + c];
    }
    if (prev_bn) {
#pragma unroll
        for (int c = 0; c < 8; c++) { sc1[c] = psc[col0 + c]; sh1[c] = psh[col0 + c]; }
    }
    float lsum[8], lsq[8];
#pragma unroll
    for (int c = 0; c < 8; c++) { lsum[c] = 0.f; lsq[c] = 0.f; }

#pragma unroll
    for (int r = 0; r < 4; r++) {
        int grow = row0 + ty * 4 + r;
        float2 ds = g_degew[grow];
        float4 xp0 = *(const float4*)&xprev[grow * H + col0];
        float4 xp1 = *(const float4*)&xprev[grow * H + col0 + 4];
        float xp[8] = {xp0.x, xp0.y, xp0.z, xp0.w, xp1.x, xp1.y, xp1.z, xp1.w};
        if (prev_bn) {
#pragma unroll
            for (int c = 0; c < 8; c++) {
                float v = fmaf(xp[c], sc1[c], sh1[c]);
                xp[c] = v > 0.f ? v : 0.01f * v;
            }
        }
#pragma unroll
        for (int c = 0; c < 8; c++) {
            float t = acc[r][c] + ds.x * cb[c] + ds.y * wev[c] + xp[c];
            acc[r][c] = t;
            lsum[c] += t;
            lsq[c] += t * t;
        }
#pragma unroll
        for (int c = 0; c < 8; c += 4) {
            float4 v;
            v.x = acc[r][c + 0]; v.y = acc[r][c + 1];
            v.z = acc[r][c + 2]; v.w = acc[r][c + 3];
            *(float4*)&out[grow * H + col0 + c] = v;
        }
    }
#pragma unroll
    for (int c = 0; c < 8; c++) {
        ps[ty * 128 + col0 + c] = lsum[c];
        pq[ty * 128 + col0 + c] = lsq[c];
    }
    __syncthreads();
    if (tid < 128) {
        float s = 0.f, q = 0.f;
#pragma unroll
        for (int y = 0; y < 16; y++) {
            s += ps[y * 128 + tid];
            q += pq[y * 128 + tid];
        }
        atomicAdd(&g_colstats[tid], s);
        atomicAdd(&g_colstats[128 + tid], q);
    }
}

// ---------------- BN stat finalize -> affine scale/shift --------------------
__global__ void finalize_kernel(const float* __restrict__ g,
                                const float* __restrict__ beta,
                                float* __restrict__ sc_out,
                                float* __restrict__ sh_out) {
    int j = threadIdx.x;
    float mu = g_colstats[j] * (1.f / (float)NN);
    float var = g_colstats[128 + j] * (1.f / (float)NN) - mu * mu;
    float rstd = rsqrtf(var + BN_EPS);
    float sc = g[j] * rstd;
    sc_out[j] = sc;
    sh_out[j] = beta[j] - mu * sc;
}

// ---------------- edge prediction (BN2 applied inline) -----------------------
__global__ void predict_kernel(const int* __restrict__ ei,
                               const int* __restrict__ em,
                               const float* __restrict__ x2raw,
                               const float* __restrict__ sc,
                               const float* __restrict__ sh,
                               float* __restrict__ out) {
    int warp = (blockIdx.x * blockDim.x + threadIdx.x) >> 5;
    int lane = threadIdx.x & 31;
    if (warp >= EPRED) return;
    float4 s2 = *(const float4*)&sc[lane * 4];
    float4 h2 = *(const float4*)&sh[lane * 4];
    int e = em[warp];
    int s = ei[e];
    int t = ei[EE + e];
    float4 a = *(const float4*)&g_xini[s * H + lane * 4];
    float4 b = *(const float4*)&x2raw[t * H + lane * 4];
    b.x = fmaf(b.x, s2.x, h2.x);
    b.y = fmaf(b.y, s2.y, h2.y);
    b.z = fmaf(b.z, s2.z, h2.z);
    b.w = fmaf(b.w, s2.w, h2.w);
    float d = a.x * b.x + a.y * b.y + a.z * b.z + a.w * b.w;
#pragma unroll
    for (int o = 16; o; o >>= 1) d += __shfl_xor_sync(0xffffffffu, d, o);
    if (lane == 0) out[warp] = 1.f / (1.f + expf(-d * (1.f / 128.f)));
}

// ---------------- launch -----------------------------------------------------
extern "C" void kernel_launch(void* const* d_in, const int* in_sizes, int n_in,
                              void* d_out, int out_size) {
    const float* qf  = (const float*)d_in[0];
    const float* lf  = (const float*)d_in[1];
    const int*   ei  = (const int*)d_in[2];
    const int*   em  = (const int*)d_in[3];
    const int*   ecs = (const int*)d_in[4];
    const float* ewt = (const float*)d_in[5];
    const float* Wq  = (const float*)d_in[6];
    const float* bq  = (const float*)d_in[7];
    const float* Wl  = (const float*)d_in[8];
    const float* bl  = (const float*)d_in[9];
    const float* Wem = (const float*)d_in[10];
    const float* bem = (const float*)d_in[11];
    const float* W1m = (const float*)d_in[12];
    const float* b1m = (const float*)d_in[13];
    const float* W1e = (const float*)d_in[14];
    const float* b1e = (const float*)d_in[15];
    const float* W2m = (const float*)d_in[16];
    const float* b2m = (const float*)d_in[17];
    const float* W2e = (const float*)d_in[18];
    const float* b2e = (const float*)d_in[19];
    const float* g1    = (const float*)d_in[20];
    const float* beta1 = (const float*)d_in[21];
    const float* g2    = (const float*)d_in[22];
    const float* beta2 = (const float*)d_in[23];
    float* out = (float*)d_out;

    void *p_agg, *p_xini, *p_x1, *p_degew, *p_colstats;
    void *p_sc1, *p_sh1, *p_sc2, *p_sh2;
    cudaGetSymbolAddress(&p_agg, g_agg);
    cudaGetSymbolAddress(&p_xini, g_xini);
    cudaGetSymbolAddress(&p_x1, g_x1);
    cudaGetSymbolAddress(&p_degew, g_degew);
    cudaGetSymbolAddress(&p_colstats, g_colstats);
    cudaGetSymbolAddress(&p_sc1, g_scale1);
    cudaGetSymbolAddress(&p_sh1, g_shift1);
    cudaGetSymbolAddress(&p_sc2, g_scale2);
    cudaGetSymbolAddress(&p_sh2, g_shift2);

    // launches 0-4 (so proj_q is capture slot 5 for ncu -s 5 -c 1)
    cudaMemsetAsync(p_degew, 0, NN * sizeof(float2));              // 0
    cudaMemsetAsync(p_agg, 0, (size_t)NN * H * sizeof(float));     // 1
    cudaMemsetAsync(p_colstats, 0, 2 * H * sizeof(float));         // 2
    proj_l_kernel<<<NL, H>>>(lf, Wl, bl);                          // 3
    edge_prep_kernel<<<(ESEE + 255) / 256, 256>>>(ei, ecs, ewt, Wem, bem); // 4
    proj_q_kernel<<<NN / 64, 256>>>(qf, Wq, bq);                   // 5 <- profiled

    // ---- layer 1 ----
    scatter_raw_kernel<<<ESEE / 8, 256>>>((const float*)p_xini, (float*)p_agg);
    layer_gemm_kernel<<<NN / 64, 256>>>((const float*)p_agg, W1m, b1m, b1e, W1e,
                                        (const float*)p_xini,
                                        nullptr, nullptr, 0, (float*)p_agg);
    finalize_kernel<<<1, H>>>(g1, beta1, (float*)p_sc1, (float*)p_sh1);

    // ---- layer 2 ----
    cudaMemsetAsync(p_x1, 0, (size_t)NN * H * sizeof(float));
    cudaMemsetAsync(p_colstats, 0, 2 * H * sizeof(float));
    scatter_bn_kernel<<<ESEE / 8, 256>>>((const float*)p_agg, (float*)p_x1,
                                         (const float*)p_sc1, (const float*)p_sh1);
    layer_gemm_kernel<<<NN / 64, 256>>>((const float*)p_x1, W2m, b2m, b2e, W2e,
                                        (const float*)p_agg,
                                        (const float*)p_sc1, (const float*)p_sh1,
                                        1, (float*)p_x1);
    finalize_kernel<<<1, H>>>(g2, beta2, (float*)p_sc2, (float*)p_sh2);

    // ---- edge prediction ----
    predict_kernel<<<EPRED / 8, 256>>>(ei, em, (const float*)p_x1,
                                       (const float*)p_sc2, (const float*)p_sh2, out);
}

// round 7
// speedup vs baseline: 2.1856x; 1.3113x over previous
#include <cuda_runtime.h>
#include <cuda_bf16.h>
#include <math.h>
#include <stdint.h>

#define NQ    100000
#define NL    32
#define NN    100032
#define QD    384
#define LD    1024
#define H     128
#define EE    1000000
#define ESEE  750000
#define EPRED 250000
#define BN_EPS 1e-5f
#define APAD  20

// proj_q mma config
#define BM 128
#define BN 128
#define BK 32
#define TSTAGES (QD / BK)        // 12
#define GRID_TC 782              // ceil(100000/128)
// dynamic smem byte offsets (bf16 tiles, padded rows)
#define A_STRIDE_B 80            // (32+8) bf16 * 2
#define B_STRIDE_B 272           // (128+8) bf16 * 2
#define AHI_OFF 0                // 2 bufs * 10240
#define ALO_OFF 20480
#define BHI_OFF 40960            // 2 bufs * 8704
#define BLO_OFF 58368
#define SMEM_PQ 75776

// ---------------- scratch (static device globals; no allocation) ------------
__device__ __align__(16) float g_xini[NN * H];
__device__ __align__(16) float g_agg [NN * H];
__device__ __align__(16) float g_x1  [NN * H];
__device__ int    g_src[ESEE];
__device__ int    g_dst[ESEE];
__device__ __align__(8) float2 g_degew[NN];
__device__ float g_colstats[2 * H];
__device__ float g_scale1[H], g_shift1[H];
__device__ float g_scale2[H], g_shift2[H];
__device__ __align__(16) __nv_bfloat16 g_whi[QD * H];
__device__ __align__(16) __nv_bfloat16 g_wlo[QD * H];

// ---------------- ptx helpers ------------------------------------------------
__device__ __forceinline__ unsigned smem_u32(const void* p) {
    return (unsigned)__cvta_generic_to_shared(p);
}
__device__ __forceinline__ void cp16(unsigned dst, const void* src) {
    asm volatile("cp.async.ca.shared.global [%0], [%1], 16;" :: "r"(dst), "l"(src));
}
#define CP_COMMIT() asm volatile("cp.async.commit_group;")

#define LDSM_X4(r0, r1, r2, r3, addr) \
    asm volatile("ldmatrix.sync.aligned.m8n8.x4.shared.b16 {%0,%1,%2,%3}, [%4];" \
                 : "=r"(r0), "=r"(r1), "=r"(r2), "=r"(r3) : "r"(addr))
#define LDSM_X4T(r0, r1, r2, r3, addr) \
    asm volatile("ldmatrix.sync.aligned.m8n8.x4.trans.shared.b16 {%0,%1,%2,%3}, [%4];" \
                 : "=r"(r0), "=r"(r1), "=r"(r2), "=r"(r3) : "r"(addr))
#define MMA_BF16(c, a, b) \
    asm volatile("mma.sync.aligned.m16n8k16.row.col.f32.bf16.bf16.f32 " \
                 "{%0,%1,%2,%3}, {%4,%5,%6,%7}, {%8,%9}, {%0,%1,%2,%3};" \
                 : "+f"((c)[0]), "+f"((c)[1]), "+f"((c)[2]), "+f"((c)[3]) \
                 : "r"((a)[0]), "r"((a)[1]), "r"((a)[2]), "r"((a)[3]), \
                   "r"((b)[0]), "r"((b)[1]))

// ---------------- W prep: fp32 -> bf16 hi/lo images ---------------------------
__global__ void prep_w_kernel(const float* __restrict__ W) {
    int idx = blockIdx.x * blockDim.x + threadIdx.x;
    if (idx >= QD * H) return;
    float w = W[idx];
    __nv_bfloat16 hi = __float2bfloat16(w);
    __nv_bfloat16 lo = __float2bfloat16(w - __bfloat162float(hi));
    g_whi[idx] = hi;
    g_wlo[idx] = lo;
}

// ---------------- proj_q via mma.sync bf16x3 ----------------------------------
__global__ void __launch_bounds__(256, 1) proj_q_mma(const float* __restrict__ A,
                                                     const float* __restrict__ bias,
                                                     float* __restrict__ out) {
    extern __shared__ char sm[];
    uint32_t sb = smem_u32(sm);
    char* smg = sm;
    int tid = threadIdx.x;
    int wid = tid >> 5;
    int lane = tid & 31;
    int wm = wid & 3;        // m offset wm*32
    int wn = wid >> 2;       // n offset wn*64
    int row0 = blockIdx.x * BM;

    float acc[2][8][4];
#pragma unroll
    for (int mt = 0; mt < 2; mt++)
#pragma unroll
        for (int nt = 0; nt < 8; nt++)
#pragma unroll
            for (int j = 0; j < 4; j++) acc[mt][nt][j] = 0.f;

    // loader indices (fixed per thread)
    int af_row[4], af_c4[4];
#pragma unroll
    for (int i = 0; i < 4; i++) {
        int f = tid + i * 256;
        af_row[i] = f >> 3;
        af_c4[i] = f & 7;
    }

    float4 av[4];
    // ---- load A stage 0 into regs
#pragma unroll
    for (int i = 0; i < 4; i++) {
        int grow = row0 + af_row[i];
        if (grow >= NQ) grow = 0;
        av[i] = *(const float4*)&A[(long)grow * QD + af_c4[i] * 4];
    }
    // ---- cp.async B stage 0
#pragma unroll
    for (int i = 0; i < 2; i++) {
        int seg = tid + i * 256;
        int br = seg >> 4, c16 = seg & 15;
        cp16(sb + BHI_OFF + br * B_STRIDE_B + c16 * 16, g_whi + br * H + c16 * 8);
        cp16(sb + BLO_OFF + br * B_STRIDE_B + c16 * 16, g_wlo + br * H + c16 * 8);
    }
    CP_COMMIT();
    // ---- convert+store A stage 0
#pragma unroll
    for (int i = 0; i < 4; i++) {
        __nv_bfloat16 h0 = __float2bfloat16(av[i].x);
        __nv_bfloat16 h1 = __float2bfloat16(av[i].y);
        __nv_bfloat16 h2 = __float2bfloat16(av[i].z);
        __nv_bfloat16 h3 = __float2bfloat16(av[i].w);
        __nv_bfloat16 l0 = __float2bfloat16(av[i].x - __bfloat162float(h0));
        __nv_bfloat16 l1 = __float2bfloat16(av[i].y - __bfloat162float(h1));
        __nv_bfloat16 l2 = __float2bfloat16(av[i].z - __bfloat162float(h2));
        __nv_bfloat16 l3 = __float2bfloat16(av[i].w - __bfloat162float(h3));
        uint2 hp, lp;
        hp.x = ((uint32_t)__bfloat16_as_ushort(h1) << 16) | __bfloat16_as_ushort(h0);
        hp.y = ((uint32_t)__bfloat16_as_ushort(h3) << 16) | __bfloat16_as_ushort(h2);
        lp.x = ((uint32_t)__bfloat16_as_ushort(l1) << 16) | __bfloat16_as_ushort(l0);
        lp.y = ((uint32_t)__bfloat16_as_ushort(l3) << 16) | __bfloat16_as_ushort(l2);
        *(uint2*)(smg + AHI_OFF + af_row[i] * A_STRIDE_B + af_c4[i] * 8) = hp;
        *(uint2*)(smg + ALO_OFF + af_row[i] * A_STRIDE_B + af_c4[i] * 8) = lp;
    }

    for (int t = 0; t < TSTAGES; t++) {
        int buf = t & 1;
        int have_next = (t + 1 < TSTAGES);
        if (have_next) {
            int k0 = (t + 1) * BK;
            int nb = buf ^ 1;
#pragma unroll
            for (int i = 0; i < 4; i++) {
                int grow = row0 + af_row[i];
                if (grow >= NQ) grow = 0;
                av[i] = *(const float4*)&A[(long)grow * QD + k0 + af_c4[i] * 4];
            }
#pragma unroll
            for (int i = 0; i < 2; i++) {
                int seg = tid + i * 256;
                int br = seg >> 4, c16 = seg & 15;
                cp16(sb + BHI_OFF + nb * 8704 + br * B_STRIDE_B + c16 * 16,
                     g_whi + (k0 + br) * H + c16 * 8);
                cp16(sb + BLO_OFF + nb * 8704 + br * B_STRIDE_B + c16 * 16,
                     g_wlo + (k0 + br) * H + c16 * 8);
            }
            CP_COMMIT();
            asm volatile("cp.async.wait_group 1;");
        } else {
            asm volatile("cp.async.wait_group 0;");
        }
        __syncthreads();

        // ---- compute on buf
        uint32_t abase_hi = sb + AHI_OFF + buf * 10240;
        uint32_t abase_lo = sb + ALO_OFF + buf * 10240;
        uint32_t bbase_hi = sb + BHI_OFF + buf * 8704;
        uint32_t bbase_lo = sb + BLO_OFF + buf * 8704;
#pragma unroll
        for (int ks = 0; ks < 2; ks++) {
            uint32_t ah[2][4], al[2][4], bh[8][2], bl[8][2];
#pragma unroll
            for (int mt = 0; mt < 2; mt++) {
                uint32_t roff = (uint32_t)((wm * 32 + mt * 16 + (lane & 15)) * A_STRIDE_B
                                           + ks * 32 + (lane >> 4) * 16);
                LDSM_X4(ah[mt][0], ah[mt][1], ah[mt][2], ah[mt][3], abase_hi + roff);
                LDSM_X4(al[mt][0], al[mt][1], al[mt][2], al[mt][3], abase_lo + roff);
            }
#pragma unroll
            for (int np = 0; np < 4; np++) {
                uint32_t boff = (uint32_t)((ks * 16 + (lane & 15)) * B_STRIDE_B
                                           + (wn * 64 + np * 16 + (lane >> 4) * 8) * 2);
                LDSM_X4T(bh[np * 2][0], bh[np * 2][1], bh[np * 2 + 1][0], bh[np * 2 + 1][1],
                         bbase_hi + boff);
                LDSM_X4T(bl[np * 2][0], bl[np * 2][1], bl[np * 2 + 1][0], bl[np * 2 + 1][1],
                         bbase_lo + boff);
            }
#pragma unroll
            for (int mt = 0; mt < 2; mt++)
#pragma unroll
                for (int nt = 0; nt < 8; nt++) {
                    MMA_BF16(acc[mt][nt], ah[mt], bh[nt]);
                    MMA_BF16(acc[mt][nt], al[mt], bh[nt]);
                    MMA_BF16(acc[mt][nt], ah[mt], bl[nt]);
                }
        }
        __syncthreads();

        if (have_next) {
            int nb = buf ^ 1;
#pragma unroll
            for (int i = 0; i < 4; i++) {
                __nv_bfloat16 h0 = __float2bfloat16(av[i].x);
                __nv_bfloat16 h1 = __float2bfloat16(av[i].y);
                __nv_bfloat16 h2 = __float2bfloat16(av[i].z);
                __nv_bfloat16 h3 = __float2bfloat16(av[i].w);
                __nv_bfloat16 l0 = __float2bfloat16(av[i].x - __bfloat162float(h0));
                __nv_bfloat16 l1 = __float2bfloat16(av[i].y - __bfloat162float(h1));
                __nv_bfloat16 l2 = __float2bfloat16(av[i].z - __bfloat162float(h2));
                __nv_bfloat16 l3 = __float2bfloat16(av[i].w - __bfloat162float(h3));
                uint2 hp, lp;
                hp.x = ((uint32_t)__bfloat16_as_ushort(h1) << 16) | __bfloat16_as_ushort(h0);
                hp.y = ((uint32_t)__bfloat16_as_ushort(h3) << 16) | __bfloat16_as_ushort(h2);
                lp.x = ((uint32_t)__bfloat16_as_ushort(l1) << 16) | __bfloat16_as_ushort(l0);
                lp.y = ((uint32_t)__bfloat16_as_ushort(l3) << 16) | __bfloat16_as_ushort(l2);
                *(uint2*)(smg + AHI_OFF + nb * 10240 + af_row[i] * A_STRIDE_B + af_c4[i] * 8) = hp;
                *(uint2*)(smg + ALO_OFF + nb * 10240 + af_row[i] * A_STRIDE_B + af_c4[i] * 8) = lp;
            }
        }
    }

    // ---- epilogue: add bias, store fp32
#pragma unroll
    for (int mt = 0; mt < 2; mt++) {
        int m0r = row0 + wm * 32 + mt * 16 + (lane >> 2);
        int m1r = m0r + 8;
#pragma unroll
        for (int nt = 0; nt < 8; nt++) {
            int n = wn * 64 + nt * 8 + (lane & 3) * 2;
            float2 bv = *(const float2*)&bias[n];
            if (m0r < NQ) {
                float2 o = make_float2(acc[mt][nt][0] + bv.x, acc[mt][nt][1] + bv.y);
                *(float2*)&out[(long)m0r * H + n] = o;
            }
            if (m1r < NQ) {
                float2 o = make_float2(acc[mt][nt][2] + bv.x, acc[mt][nt][3] + bv.y);
                *(float2*)&out[(long)m1r * H + n] = o;
            }
        }
    }
}

// ---------------- llm projection (tiny: 32 rows, K=1024) --------------------
__global__ void proj_l_kernel(const float* __restrict__ A,
                              const float* __restrict__ W,
                              const float* __restrict__ b) {
    int i = blockIdx.x;
    int j = threadIdx.x;
    float acc = b[j];
    for (int k = 0; k < LD; k++) acc += A[i * LD + k] * W[k * H + j];
    g_xini[(NQ + i) * H + j] = acc;
}

// ---------------- edge prep --------------------------------------------------
__global__ void edge_prep_kernel(const int* __restrict__ ei,
                                 const int* __restrict__ ecs,
                                 const float* __restrict__ ewt,
                                 const float* __restrict__ Wem,
                                 const float* __restrict__ bem) {
    int i = blockIdx.x * blockDim.x + threadIdx.x;
    if (i >= ESEE) return;
    int e = ecs[i];
    int s = ei[e];
    int d = ei[EE + e];
    g_src[i] = s;
    g_dst[i] = d;
    float v = ewt[e] * Wem[0] + bem[0];
    v = v > 0.f ? v : 0.01f * v;
    asm volatile("red.global.add.v2.f32 [%0], {%1, %2};"
                 :: "l"(&g_degew[d]), "f"(1.0f), "f"(v) : "memory");
}

// ---------------- scatter-add (raw rows) -------------------------------------
__global__ void __launch_bounds__(256) scatter_raw_kernel(const float* __restrict__ x,
                                                          float* __restrict__ outbuf) {
    int e = blockIdx.x * 8 + (threadIdx.x >> 5);
    int lane = threadIdx.x & 31;
    int s = g_src[e];
    int d = g_dst[e];
    float4 v = *(const float4*)&x[s * H + lane * 4];
    asm volatile("red.global.add.v4.f32 [%0], {%1, %2, %3, %4};"
                 :: "l"(&outbuf[d * H + lane * 4]),
                    "f"(v.x), "f"(v.y), "f"(v.z), "f"(v.w) : "memory");
}

// ---------------- scatter-add with inline BN + leaky relu --------------------
__global__ void __launch_bounds__(256) scatter_bn_kernel(const float* __restrict__ x,
                                                         float* __restrict__ outbuf,
                                                         const float* __restrict__ sc,
                                                         const float* __restrict__ sh) {
    int e = blockIdx.x * 8 + (threadIdx.x >> 5);
    int lane = threadIdx.x & 31;
    float4 s4 = *(const float4*)&sc[lane * 4];
    float4 h4 = *(const float4*)&sh[lane * 4];
    int s = g_src[e];
    int d = g_dst[e];
    float4 v = *(const float4*)&x[s * H + lane * 4];
    v.x = fmaf(v.x, s4.x, h4.x); v.x = v.x > 0.f ? v.x : 0.01f * v.x;
    v.y = fmaf(v.y, s4.y, h4.y); v.y = v.y > 0.f ? v.y : 0.01f * v.y;
    v.z = fmaf(v.z, s4.z, h4.z); v.z = v.z > 0.f ? v.z : 0.01f * v.z;
    v.w = fmaf(v.w, s4.w, h4.w); v.w = v.w > 0.f ? v.w : 0.01f * v.w;
    asm volatile("red.global.add.v4.f32 [%0], {%1, %2, %3, %4};"
                 :: "l"(&outbuf[d * H + lane * 4]),
                    "f"(v.x), "f"(v.y), "f"(v.z), "f"(v.w) : "memory");
}

// ---------------- layer GEMM + epilogue + BN column stats -------------------
__device__ __forceinline__ unsigned smem_u32b(const void* p) {
    return (unsigned)__cvta_generic_to_shared(p);
}
__global__ void __launch_bounds__(256) layer_gemm_kernel(const float* __restrict__ Ain,
                                  const float* __restrict__ W,
                                  const float* __restrict__ bm,
                                  const float* __restrict__ be,
                                  const float* __restrict__ We,
                                  const float* __restrict__ xprev,
                                  const float* __restrict__ psc,
                                  const float* __restrict__ psh,
                                  int prev_bn,
                                  float* __restrict__ out) {
    __shared__ __align__(16) float As[2][64 * APAD];
    __shared__ __align__(16) float Ws[2][16 * 128];
    __shared__ float ps[16 * 128];
    __shared__ float pq[16 * 128];
    int tid = threadIdx.x;
    int tx = tid & 15;
    int ty = tid >> 4;
    int row0 = blockIdx.x * 64;

    int ar = tid >> 2, ac = (tid & 3) * 4;
    int wr = tid >> 5, wc = (tid & 31) * 4;
    const float* aptr = Ain + (long)(row0 + ar) * H + ac;

    float acc[4][8];
#pragma unroll
    for (int r = 0; r < 4; r++)
#pragma unroll
        for (int c = 0; c < 8; c++) acc[r][c] = 0.f;

    cp16(smem_u32b(&As[0][ar * APAD + ac]), aptr);
    cp16(smem_u32b(&Ws[0][wr * 128 + wc]), &W[wr * H + wc]);
    cp16(smem_u32b(&Ws[0][(wr + 8) * 128 + wc]), &W[(wr + 8) * H + wc]);
    CP_COMMIT();

    const int T = H / 16;
    for (int t = 0; t < T; t++) {
        int buf = t & 1;
        if (t + 1 < T) {
            int nb = buf ^ 1;
            int k0 = (t + 1) * 16;
            cp16(smem_u32b(&As[nb][ar * APAD + ac]), aptr + k0);
            cp16(smem_u32b(&Ws[nb][wr * 128 + wc]), &W[(k0 + wr) * H + wc]);
            cp16(smem_u32b(&Ws[nb][(wr + 8) * 128 + wc]), &W[(k0 + wr + 8) * H + wc]);
            CP_COMMIT();
            asm volatile("cp.async.wait_group 1;");
        } else {
            asm volatile("cp.async.wait_group 0;");
        }
        __syncthreads();
#pragma unroll
        for (int k = 0; k < 16; k++) {
            float a[4];
#pragma unroll
            for (int r = 0; r < 4; r++) a[r] = As[buf][(ty * 4 + r) * APAD + k];
            float4 b0 = *(const float4*)&Ws[buf][k * 128 + tx * 8];
            float4 b1 = *(const float4*)&Ws[buf][k * 128 + tx * 8 + 4];
            float b[8] = {b0.x, b0.y, b0.z, b0.w, b1.x, b1.y, b1.z, b1.w};
#pragma unroll
            for (int r = 0; r < 4; r++)
#pragma unroll
                for (int c = 0; c < 8; c++) acc[r][c] += a[r] * b[c];
        }
        __syncthreads();
    }

    int col0 = tx * 8;
    float cb[8], wev[8], sc1[8], sh1[8];
#pragma unroll
    for (int c = 0; c < 8; c++) {
        cb[c]  = bm[col0 + c] + be[col0 + c];
        wev[c] = We[col0 + c];
    }
    if (prev_bn) {
#pragma unroll
        for (int c = 0; c < 8; c++) { sc1[c] = psc[col0 + c]; sh1[c] = psh[col0 + c]; }
    }
    float lsum[8], lsq[8];
#pragma unroll
    for (int c = 0; c < 8; c++) { lsum[c] = 0.f; lsq[c] = 0.f; }

#pragma unroll
    for (int r = 0; r < 4; r++) {
        int grow = row0 + ty * 4 + r;
        float2 ds = g_degew[grow];
        float4 xp0 = *(const float4*)&xprev[grow * H + col0];
        float4 xp1 = *(const float4*)&xprev[grow * H + col0 + 4];
        float xp[8] = {xp0.x, xp0.y, xp0.z, xp0.w, xp1.x, xp1.y, xp1.z, xp1.w};
        if (prev_bn) {
#pragma unroll
            for (int c = 0; c < 8; c++) {
                float v = fmaf(xp[c], sc1[c], sh1[c]);
                xp[c] = v > 0.f ? v : 0.01f * v;
            }
        }
#pragma unroll
        for (int c = 0; c < 8; c++) {
            float t = acc[r][c] + ds.x * cb[c] + ds.y * wev[c] + xp[c];
            acc[r][c] = t;
            lsum[c] += t;
            lsq[c] += t * t;
        }
#pragma unroll
        for (int c = 0; c < 8; c += 4) {
            float4 v;
            v.x = acc[r][c + 0]; v.y = acc[r][c + 1];
            v.z = acc[r][c + 2]; v.w = acc[r][c + 3];
            *(float4*)&out[grow * H + col0 + c] = v;
        }
    }
#pragma unroll
    for (int c = 0; c < 8; c++) {
        ps[ty * 128 + col0 + c] = lsum[c];
        pq[ty * 128 + col0 + c] = lsq[c];
    }
    __syncthreads();
    if (tid < 128) {
        float s = 0.f, q = 0.f;
#pragma unroll
        for (int y = 0; y < 16; y++) {
            s += ps[y * 128 + tid];
            q += pq[y * 128 + tid];
        }
        atomicAdd(&g_colstats[tid], s);
        atomicAdd(&g_colstats[128 + tid], q);
    }
}

// ---------------- BN stat finalize -------------------------------------------
__global__ void finalize_kernel(const float* __restrict__ g,
                                const float* __restrict__ beta,
                                float* __restrict__ sc_out,
                                float* __restrict__ sh_out) {
    int j = threadIdx.x;
    float mu = g_colstats[j] * (1.f / (float)NN);
    float var = g_colstats[128 + j] * (1.f / (float)NN) - mu * mu;
    float rstd = rsqrtf(var + BN_EPS);
    float sc = g[j] * rstd;
    sc_out[j] = sc;
    sh_out[j] = beta[j] - mu * sc;
}

// ---------------- edge prediction (BN2 inline) --------------------------------
__global__ void predict_kernel(const int* __restrict__ ei,
                               const int* __restrict__ em,
                               const float* __restrict__ x2raw,
                               const float* __restrict__ sc,
                               const float* __restrict__ sh,
                               float* __restrict__ out) {
    int warp = (blockIdx.x * blockDim.x + threadIdx.x) >> 5;
    int lane = threadIdx.x & 31;
    if (warp >= EPRED) return;
    float4 s2 = *(const float4*)&sc[lane * 4];
    float4 h2 = *(const float4*)&sh[lane * 4];
    int e = em[warp];
    int s = ei[e];
    int t = ei[EE + e];
    float4 a = *(const float4*)&g_xini[s * H + lane * 4];
    float4 b = *(const float4*)&x2raw[t * H + lane * 4];
    b.x = fmaf(b.x, s2.x, h2.x);
    b.y = fmaf(b.y, s2.y, h2.y);
    b.z = fmaf(b.z, s2.z, h2.z);
    b.w = fmaf(b.w, s2.w, h2.w);
    float d = a.x * b.x + a.y * b.y + a.z * b.z + a.w * b.w;
#pragma unroll
    for (int o = 16; o; o >>= 1) d += __shfl_xor_sync(0xffffffffu, d, o);
    if (lane == 0) out[warp] = 1.f / (1.f + expf(-d * (1.f / 128.f)));
}

// ---------------- launch -----------------------------------------------------
extern "C" void kernel_launch(void* const* d_in, const int* in_sizes, int n_in,
                              void* d_out, int out_size) {
    const float* qf  = (const float*)d_in[0];
    const float* lf  = (const float*)d_in[1];
    const int*   ei  = (const int*)d_in[2];
    const int*   em  = (const int*)d_in[3];
    const int*   ecs = (const int*)d_in[4];
    const float* ewt = (const float*)d_in[5];
    const float* Wq  = (const float*)d_in[6];
    const float* bq  = (const float*)d_in[7];
    const float* Wl  = (const float*)d_in[8];
    const float* bl  = (const float*)d_in[9];
    const float* Wem = (const float*)d_in[10];
    const float* bem = (const float*)d_in[11];
    const float* W1m = (const float*)d_in[12];
    const float* b1m = (const float*)d_in[13];
    const float* W1e = (const float*)d_in[14];
    const float* b1e = (const float*)d_in[15];
    const float* W2m = (const float*)d_in[16];
    const float* b2m = (const float*)d_in[17];
    const float* W2e = (const float*)d_in[18];
    const float* b2e = (const float*)d_in[19];
    const float* g1    = (const float*)d_in[20];
    const float* beta1 = (const float*)d_in[21];
    const float* g2    = (const float*)d_in[22];
    const float* beta2 = (const float*)d_in[23];
    float* out = (float*)d_out;

    void *p_agg, *p_xini, *p_x1, *p_degew, *p_colstats;
    void *p_sc1, *p_sh1, *p_sc2, *p_sh2;
    cudaGetSymbolAddress(&p_agg, g_agg);
    cudaGetSymbolAddress(&p_xini, g_xini);
    cudaGetSymbolAddress(&p_x1, g_x1);
    cudaGetSymbolAddress(&p_degew, g_degew);
    cudaGetSymbolAddress(&p_colstats, g_colstats);
    cudaGetSymbolAddress(&p_sc1, g_scale1);
    cudaGetSymbolAddress(&p_sh1, g_shift1);
    cudaGetSymbolAddress(&p_sc2, g_scale2);
    cudaGetSymbolAddress(&p_sh2, g_shift2);

    static int smem_set = 0;
    if (!smem_set) {
        cudaFuncSetAttribute(proj_q_mma, cudaFuncAttributeMaxDynamicSharedMemorySize,
                             SMEM_PQ);
        smem_set = 1;
    }

    cudaMemsetAsync(p_degew, 0, NN * sizeof(float2));
    cudaMemsetAsync(p_agg, 0, (size_t)NN * H * sizeof(float));
    cudaMemsetAsync(p_colstats, 0, 2 * H * sizeof(float));

    proj_l_kernel<<<NL, H>>>(lf, Wl, bl);
    edge_prep_kernel<<<(ESEE + 255) / 256, 256>>>(ei, ecs, ewt, Wem, bem);
    prep_w_kernel<<<(QD * H + 255) / 256, 256>>>(Wq);
    proj_q_mma<<<GRID_TC, 256, SMEM_PQ>>>(qf, bq, (float*)p_xini);

    // ---- layer 1 ----
    scatter_raw_kernel<<<ESEE / 8, 256>>>((const float*)p_xini, (float*)p_agg);
    layer_gemm_kernel<<<NN / 64, 256>>>((const float*)p_agg, W1m, b1m, b1e, W1e,
                                        (const float*)p_xini,
                                        nullptr, nullptr, 0, (float*)p_agg);
    finalize_kernel<<<1, H>>>(g1, beta1, (float*)p_sc1, (float*)p_sh1);

    // ---- layer 2 ----
    cudaMemsetAsync(p_x1, 0, (size_t)NN * H * sizeof(float));
    cudaMemsetAsync(p_colstats, 0, 2 * H * sizeof(float));
    scatter_bn_kernel<<<ESEE / 8, 256>>>((const float*)p_agg, (float*)p_x1,
                                         (const float*)p_sc1, (const float*)p_sh1);
    layer_gemm_kernel<<<NN / 64, 256>>>((const float*)p_x1, W2m, b2m, b2e, W2e,
                                        (const float*)p_agg,
                                        (const float*)p_sc1, (const float*)p_sh1,
                                        1, (float*)p_x1);
    finalize_kernel<<<1, H>>>(g2, beta2, (float*)p_sc2, (float*)p_sh2);

    // ---- edge prediction ----
    predict_kernel<<<EPRED / 8, 256>>>(ei, em, (const float*)p_x1,
                                       (const float*)p_sc2, (const float*)p_sh2, out);
}

// round 8
// speedup vs baseline: 2.4290x; 1.1114x over previous
#include <cuda_runtime.h>
#include <cuda_bf16.h>
#include <math.h>
#include <stdint.h>

#define NQ    100000
#define NL    32
#define NN    100032
#define QD    384
#define LD    1024
#define H     128
#define EE    1000000
#define ESEE  750000
#define EPRED 250000
#define BN_EPS 1e-5f

// mma tile config (shared by proj_q and layer gemms)
#define BM 128
#define BK 32
#define GRID_TC 782              // ceil(100032/128) = ceil(100000/128) = 782
#define A_STRIDE_B 80            // (32+8) bf16 * 2
#define B_STRIDE_B 272           // (128+8) bf16 * 2
#define AHI_OFF 0                // 2 bufs * 10240
#define ALO_OFF 20480
#define BHI_OFF 40960            // 2 bufs * 8704
#define BLO_OFF 58368
#define SMEM_MMA 75776

// ---------------- scratch (static device globals; no allocation) ------------
__device__ __align__(16) float g_xini[NN * H];
__device__ __align__(16) float g_agg [NN * H];
__device__ __align__(16) float g_x1  [NN * H];
__device__ int    g_src[ESEE];
__device__ int    g_dst[ESEE];
__device__ __align__(8) float2 g_degew[NN];
__device__ __align__(8) float2 g_colstats2[H];   // per-col (sum, sumsq)
__device__ float g_scale1[H], g_shift1[H];
__device__ float g_scale2[H], g_shift2[H];
__device__ __align__(16) __nv_bfloat16 g_wqhi[QD * H], g_wqlo[QD * H];
__device__ __align__(16) __nv_bfloat16 g_w1hi[H * H],  g_w1lo[H * H];
__device__ __align__(16) __nv_bfloat16 g_w2hi[H * H],  g_w2lo[H * H];

// ---------------- ptx helpers ------------------------------------------------
__device__ __forceinline__ unsigned smem_u32(const void* p) {
    return (unsigned)__cvta_generic_to_shared(p);
}
__device__ __forceinline__ void cp16(unsigned dst, const void* src) {
    asm volatile("cp.async.ca.shared.global [%0], [%1], 16;" :: "r"(dst), "l"(src));
}
#define CP_COMMIT() asm volatile("cp.async.commit_group;")

#define LDSM_X4(r0, r1, r2, r3, addr) \
    asm volatile("ldmatrix.sync.aligned.m8n8.x4.shared.b16 {%0,%1,%2,%3}, [%4];" \
                 : "=r"(r0), "=r"(r1), "=r"(r2), "=r"(r3) : "r"(addr))
#define LDSM_X4T(r0, r1, r2, r3, addr) \
    asm volatile("ldmatrix.sync.aligned.m8n8.x4.trans.shared.b16 {%0,%1,%2,%3}, [%4];" \
                 : "=r"(r0), "=r"(r1), "=r"(r2), "=r"(r3) : "r"(addr))
#define MMA_BF16(c, a, b) \
    asm volatile("mma.sync.aligned.m16n8k16.row.col.f32.bf16.bf16.f32 " \
                 "{%0,%1,%2,%3}, {%4,%5,%6,%7}, {%8,%9}, {%0,%1,%2,%3};" \
                 : "+f"((c)[0]), "+f"((c)[1]), "+f"((c)[2]), "+f"((c)[3]) \
                 : "r"((a)[0]), "r"((a)[1]), "r"((a)[2]), "r"((a)[3]), \
                   "r"((b)[0]), "r"((b)[1]))

__device__ __forceinline__ void split_store(char* smg, int off_hi, int off_lo,
                                            int row, int c4, float4 v) {
    __nv_bfloat16 h0 = __float2bfloat16(v.x);
    __nv_bfloat16 h1 = __float2bfloat16(v.y);
    __nv_bfloat16 h2 = __float2bfloat16(v.z);
    __nv_bfloat16 h3 = __float2bfloat16(v.w);
    __nv_bfloat16 l0 = __float2bfloat16(v.x - __bfloat162float(h0));
    __nv_bfloat16 l1 = __float2bfloat16(v.y - __bfloat162float(h1));
    __nv_bfloat16 l2 = __float2bfloat16(v.z - __bfloat162float(h2));
    __nv_bfloat16 l3 = __float2bfloat16(v.w - __bfloat162float(h3));
    uint2 hp, lp;
    hp.x = ((uint32_t)__bfloat16_as_ushort(h1) << 16) | __bfloat16_as_ushort(h0);
    hp.y = ((uint32_t)__bfloat16_as_ushort(h3) << 16) | __bfloat16_as_ushort(h2);
    lp.x = ((uint32_t)__bfloat16_as_ushort(l1) << 16) | __bfloat16_as_ushort(l0);
    lp.y = ((uint32_t)__bfloat16_as_ushort(l3) << 16) | __bfloat16_as_ushort(l2);
    *(uint2*)(smg + off_hi + row * A_STRIDE_B + c4 * 8) = hp;
    *(uint2*)(smg + off_lo + row * A_STRIDE_B + c4 * 8) = lp;
}

// ---------------- W prep: all three weights -> bf16 hi/lo --------------------
__global__ void prep_all_kernel(const float* __restrict__ Wq,
                                const float* __restrict__ W1,
                                const float* __restrict__ W2) {
    int idx = blockIdx.x * blockDim.x + threadIdx.x;
    const int NQW = QD * H, NW = H * H;
    float w;
    __nv_bfloat16 *dhi, *dlo;
    int j;
    if (idx < NQW)                { w = Wq[idx]; dhi = g_wqhi; dlo = g_wqlo; j = idx; }
    else if (idx < NQW + NW)      { j = idx - NQW; w = W1[j]; dhi = g_w1hi; dlo = g_w1lo; }
    else if (idx < NQW + 2 * NW)  { j = idx - NQW - NW; w = W2[j]; dhi = g_w2hi; dlo = g_w2lo; }
    else return;
    __nv_bfloat16 hi = __float2bfloat16(w);
    dhi[j] = hi;
    dlo[j] = __float2bfloat16(w - __bfloat162float(hi));
}

// ---------------- proj_q via mma.sync bf16x3 ----------------------------------
__global__ void __launch_bounds__(256, 1) proj_q_mma(const float* __restrict__ A,
                                                     const float* __restrict__ bias,
                                                     float* __restrict__ out) {
    extern __shared__ char sm[];
    uint32_t sb = smem_u32(sm);
    char* smg = sm;
    int tid = threadIdx.x;
    int wid = tid >> 5;
    int lane = tid & 31;
    int wm = wid & 3;
    int wn = wid >> 2;
    int row0 = blockIdx.x * BM;

    float acc[2][8][4];
#pragma unroll
    for (int mt = 0; mt < 2; mt++)
#pragma unroll
        for (int nt = 0; nt < 8; nt++)
#pragma unroll
            for (int j = 0; j < 4; j++) acc[mt][nt][j] = 0.f;

    int af_row[4], af_c4[4];
#pragma unroll
    for (int i = 0; i < 4; i++) {
        int f = tid + i * 256;
        af_row[i] = f >> 3;
        af_c4[i] = f & 7;
    }

    float4 av[4];
#pragma unroll
    for (int i = 0; i < 4; i++) {
        int grow = row0 + af_row[i];
        if (grow >= NQ) grow = 0;
        av[i] = *(const float4*)&A[(long)grow * QD + af_c4[i] * 4];
    }
#pragma unroll
    for (int i = 0; i < 2; i++) {
        int seg = tid + i * 256;
        int br = seg >> 4, c16 = seg & 15;
        cp16(sb + BHI_OFF + br * B_STRIDE_B + c16 * 16, g_wqhi + br * H + c16 * 8);
        cp16(sb + BLO_OFF + br * B_STRIDE_B + c16 * 16, g_wqlo + br * H + c16 * 8);
    }
    CP_COMMIT();
#pragma unroll
    for (int i = 0; i < 4; i++)
        split_store(smg, AHI_OFF, ALO_OFF, af_row[i], af_c4[i], av[i]);

    const int TST = QD / BK;  // 12
    for (int t = 0; t < TST; t++) {
        int buf = t & 1;
        int have_next = (t + 1 < TST);
        if (have_next) {
            int k0 = (t + 1) * BK;
            int nb = buf ^ 1;
#pragma unroll
            for (int i = 0; i < 4; i++) {
                int grow = row0 + af_row[i];
                if (grow >= NQ) grow = 0;
                av[i] = *(const float4*)&A[(long)grow * QD + k0 + af_c4[i] * 4];
            }
#pragma unroll
            for (int i = 0; i < 2; i++) {
                int seg = tid + i * 256;
                int br = seg >> 4, c16 = seg & 15;
                cp16(sb + BHI_OFF + nb * 8704 + br * B_STRIDE_B + c16 * 16,
                     g_wqhi + (k0 + br) * H + c16 * 8);
                cp16(sb + BLO_OFF + nb * 8704 + br * B_STRIDE_B + c16 * 16,
                     g_wqlo + (k0 + br) * H + c16 * 8);
            }
            CP_COMMIT();
            asm volatile("cp.async.wait_group 1;");
        } else {
            asm volatile("cp.async.wait_group 0;");
        }
        __syncthreads();

        uint32_t abase_hi = sb + AHI_OFF + buf * 10240;
        uint32_t abase_lo = sb + ALO_OFF + buf * 10240;
        uint32_t bbase_hi = sb + BHI_OFF + buf * 8704;
        uint32_t bbase_lo = sb + BLO_OFF + buf * 8704;
#pragma unroll
        for (int ks = 0; ks < 2; ks++) {
            uint32_t ah[2][4], al[2][4], bh[8][2], bl[8][2];
#pragma unroll
            for (int mt = 0; mt < 2; mt++) {
                uint32_t roff = (uint32_t)((wm * 32 + mt * 16 + (lane & 15)) * A_STRIDE_B
                                           + ks * 32 + (lane >> 4) * 16);
                LDSM_X4(ah[mt][0], ah[mt][1], ah[mt][2], ah[mt][3], abase_hi + roff);
                LDSM_X4(al[mt][0], al[mt][1], al[mt][2], al[mt][3], abase_lo + roff);
            }
#pragma unroll
            for (int np = 0; np < 4; np++) {
                uint32_t boff = (uint32_t)((ks * 16 + (lane & 15)) * B_STRIDE_B
                                           + (wn * 64 + np * 16 + (lane >> 4) * 8) * 2);
                LDSM_X4T(bh[np * 2][0], bh[np * 2][1], bh[np * 2 + 1][0], bh[np * 2 + 1][1],
                         bbase_hi + boff);
                LDSM_X4T(bl[np * 2][0], bl[np * 2][1], bl[np * 2 + 1][0], bl[np * 2 + 1][1],
                         bbase_lo + boff);
            }
#pragma unroll
            for (int mt = 0; mt < 2; mt++)
#pragma unroll
                for (int nt = 0; nt < 8; nt++) {
                    MMA_BF16(acc[mt][nt], ah[mt], bh[nt]);
                    MMA_BF16(acc[mt][nt], al[mt], bh[nt]);
                    MMA_BF16(acc[mt][nt], ah[mt], bl[nt]);
                }
        }
        __syncthreads();

        if (have_next) {
            int nb = buf ^ 1;
#pragma unroll
            for (int i = 0; i < 4; i++)
                split_store(smg, AHI_OFF + nb * 10240, ALO_OFF + nb * 10240,
                            af_row[i], af_c4[i], av[i]);
        }
    }

#pragma unroll
    for (int mt = 0; mt < 2; mt++) {
        int m0r = row0 + wm * 32 + mt * 16 + (lane >> 2);
        int m1r = m0r + 8;
#pragma unroll
        for (int nt = 0; nt < 8; nt++) {
            int n = wn * 64 + nt * 8 + (lane & 3) * 2;
            float2 bv = *(const float2*)&bias[n];
            if (m0r < NQ) {
                float2 o = make_float2(acc[mt][nt][0] + bv.x, acc[mt][nt][1] + bv.y);
                *(float2*)&out[(long)m0r * H + n] = o;
            }
            if (m1r < NQ) {
                float2 o = make_float2(acc[mt][nt][2] + bv.x, acc[mt][nt][3] + bv.y);
                *(float2*)&out[(long)m1r * H + n] = o;
            }
        }
    }
}

// ---------------- layer GEMM via mma.sync bf16x3 + fused epilogue ------------
__global__ void __launch_bounds__(256, 1) layer_gemm_mma(
        const float* __restrict__ Ain,
        const __nv_bfloat16* __restrict__ Whi,
        const __nv_bfloat16* __restrict__ Wlo,
        const float* __restrict__ bm, const float* __restrict__ be,
        const float* __restrict__ We,
        const float* __restrict__ xprev,
        const float* __restrict__ psc, const float* __restrict__ psh,
        int prev_bn,
        float* __restrict__ out,
        float* __restrict__ zbuf) {
    extern __shared__ char sm[];
    uint32_t sb = smem_u32(sm);
    char* smg = sm;
    int tid = threadIdx.x;
    int wid = tid >> 5;
    int lane = tid & 31;
    int wm = wid & 3;
    int wn = wid >> 2;
    int row0 = blockIdx.x * BM;

    float acc[2][8][4];
#pragma unroll
    for (int mt = 0; mt < 2; mt++)
#pragma unroll
        for (int nt = 0; nt < 8; nt++)
#pragma unroll
            for (int j = 0; j < 4; j++) acc[mt][nt][j] = 0.f;

    int af_row[4], af_c4[4];
#pragma unroll
    for (int i = 0; i < 4; i++) {
        int f = tid + i * 256;
        af_row[i] = f >> 3;
        af_c4[i] = f & 7;
    }

    float4 av[4];
#pragma unroll
    for (int i = 0; i < 4; i++) {
        int grow = row0 + af_row[i];
        if (grow >= NN) grow = 0;
        av[i] = *(const float4*)&Ain[(long)grow * H + af_c4[i] * 4];
    }
#pragma unroll
    for (int i = 0; i < 2; i++) {
        int seg = tid + i * 256;
        int br = seg >> 4, c16 = seg & 15;
        cp16(sb + BHI_OFF + br * B_STRIDE_B + c16 * 16, Whi + br * H + c16 * 8);
        cp16(sb + BLO_OFF + br * B_STRIDE_B + c16 * 16, Wlo + br * H + c16 * 8);
    }
    CP_COMMIT();
#pragma unroll
    for (int i = 0; i < 4; i++)
        split_store(smg, AHI_OFF, ALO_OFF, af_row[i], af_c4[i], av[i]);

    const int TST = H / BK;  // 4
    for (int t = 0; t < TST; t++) {
        int buf = t & 1;
        int have_next = (t + 1 < TST);
        if (have_next) {
            int k0 = (t + 1) * BK;
            int nb = buf ^ 1;
#pragma unroll
            for (int i = 0; i < 4; i++) {
                int grow = row0 + af_row[i];
                if (grow >= NN) grow = 0;
                av[i] = *(const float4*)&Ain[(long)grow * H + k0 + af_c4[i] * 4];
            }
#pragma unroll
            for (int i = 0; i < 2; i++) {
                int seg = tid + i * 256;
                int br = seg >> 4, c16 = seg & 15;
                cp16(sb + BHI_OFF + nb * 8704 + br * B_STRIDE_B + c16 * 16,
                     Whi + (k0 + br) * H + c16 * 8);
                cp16(sb + BLO_OFF + nb * 8704 + br * B_STRIDE_B + c16 * 16,
                     Wlo + (k0 + br) * H + c16 * 8);
            }
            CP_COMMIT();
            asm volatile("cp.async.wait_group 1;");
        } else {
            asm volatile("cp.async.wait_group 0;");
        }
        __syncthreads();

        uint32_t abase_hi = sb + AHI_OFF + buf * 10240;
        uint32_t abase_lo = sb + ALO_OFF + buf * 10240;
        uint32_t bbase_hi = sb + BHI_OFF + buf * 8704;
        uint32_t bbase_lo = sb + BLO_OFF + buf * 8704;
#pragma unroll
        for (int ks = 0; ks < 2; ks++) {
            uint32_t ah[2][4], al[2][4], bh[8][2], bl[8][2];
#pragma unroll
            for (int mt = 0; mt < 2; mt++) {
                uint32_t roff = (uint32_t)((wm * 32 + mt * 16 + (lane & 15)) * A_STRIDE_B
                                           + ks * 32 + (lane >> 4) * 16);
                LDSM_X4(ah[mt][0], ah[mt][1], ah[mt][2], ah[mt][3], abase_hi + roff);
                LDSM_X4(al[mt][0], al[mt][1], al[mt][2], al[mt][3], abase_lo + roff);
            }
#pragma unroll
            for (int np = 0; np < 4; np++) {
                uint32_t boff = (uint32_t)((ks * 16 + (lane & 15)) * B_STRIDE_B
                                           + (wn * 64 + np * 16 + (lane >> 4) * 8) * 2);
                LDSM_X4T(bh[np * 2][0], bh[np * 2][1], bh[np * 2 + 1][0], bh[np * 2 + 1][1],
                         bbase_hi + boff);
                LDSM_X4T(bl[np * 2][0], bl[np * 2][1], bl[np * 2 + 1][0], bl[np * 2 + 1][1],
                         bbase_lo + boff);
            }
#pragma unroll
            for (int mt = 0; mt < 2; mt++)
#pragma unroll
                for (int nt = 0; nt < 8; nt++) {
                    MMA_BF16(acc[mt][nt], ah[mt], bh[nt]);
                    MMA_BF16(acc[mt][nt], al[mt], bh[nt]);
                    MMA_BF16(acc[mt][nt], ah[mt], bl[nt]);
                }
        }
        __syncthreads();

        if (have_next) {
            int nb = buf ^ 1;
#pragma unroll
            for (int i = 0; i < 4; i++)
                split_store(smg, AHI_OFF + nb * 10240, ALO_OFF + nb * 10240,
                            af_row[i], af_c4[i], av[i]);
        }
    }

    // ---- fused epilogue: deg/sumew/residual + BN column stats ----
    int lq = lane & 3;
    int lr = lane >> 2;
    float2 ds[2][2];
    bool rv[2][2];
#pragma unroll
    for (int mt = 0; mt < 2; mt++)
#pragma unroll
        for (int hf = 0; hf < 2; hf++) {
            int row = row0 + wm * 32 + mt * 16 + hf * 8 + lr;
            rv[mt][hf] = (row < NN);
            ds[mt][hf] = rv[mt][hf] ? g_degew[row] : make_float2(0.f, 0.f);
        }

#pragma unroll
    for (int nt = 0; nt < 8; nt++) {
        int n = wn * 64 + nt * 8 + lq * 2;
        float2 cb2 = make_float2(bm[n] + be[n], bm[n + 1] + be[n + 1]);
        float2 we2 = *(const float2*)&We[n];
        float2 sc2 = make_float2(0.f, 0.f), sh2 = make_float2(0.f, 0.f);
        if (prev_bn) {
            sc2 = make_float2(psc[n], psc[n + 1]);
            sh2 = make_float2(psh[n], psh[n + 1]);
        }
        float cs0 = 0.f, cs1 = 0.f, cq0 = 0.f, cq1 = 0.f;
#pragma unroll
        for (int mt = 0; mt < 2; mt++)
#pragma unroll
            for (int hf = 0; hf < 2; hf++) {
                if (rv[mt][hf]) {
                    int row = row0 + wm * 32 + mt * 16 + hf * 8 + lr;
                    float2 xp = *(const float2*)&xprev[(long)row * H + n];
                    if (prev_bn) {
                        float u0 = fmaf(xp.x, sc2.x, sh2.x);
                        float u1 = fmaf(xp.y, sc2.y, sh2.y);
                        xp.x = u0 > 0.f ? u0 : 0.01f * u0;
                        xp.y = u1 > 0.f ? u1 : 0.01f * u1;
                    }
                    float2 dd = ds[mt][hf];
                    float v0 = acc[mt][nt][hf * 2 + 0] + dd.x * cb2.x + dd.y * we2.x + xp.x;
                    float v1 = acc[mt][nt][hf * 2 + 1] + dd.x * cb2.y + dd.y * we2.y + xp.y;
                    *(float2*)&out[(long)row * H + n] = make_float2(v0, v1);
                    cs0 += v0; cq0 += v0 * v0;
                    cs1 += v1; cq1 += v1 * v1;
                }
            }
#pragma unroll
        for (int off = 4; off <= 16; off <<= 1) {
            cs0 += __shfl_xor_sync(0xffffffffu, cs0, off);
            cq0 += __shfl_xor_sync(0xffffffffu, cq0, off);
            cs1 += __shfl_xor_sync(0xffffffffu, cs1, off);
            cq1 += __shfl_xor_sync(0xffffffffu, cq1, off);
        }
        if (lr == 0) {
            asm volatile("red.global.add.v2.f32 [%0], {%1, %2};"
                         :: "l"(&g_colstats2[n]), "f"(cs0), "f"(cq0) : "memory");
            asm volatile("red.global.add.v2.f32 [%0], {%1, %2};"
                         :: "l"(&g_colstats2[n + 1]), "f"(cs1), "f"(cq1) : "memory");
        }
    }

    // ---- optional: zero next scatter target tile ----
    if (zbuf) {
        float4 z = make_float4(0.f, 0.f, 0.f, 0.f);
        for (int i = tid; i < 128 * 32; i += 256) {
            int r = row0 + (i >> 5);
            if (r < NN) *(float4*)&zbuf[(long)r * H + (i & 31) * 4] = z;
        }
    }
}

// ---------------- llm projection (tiny: 32 rows, K=1024) --------------------
__global__ void proj_l_kernel(const float* __restrict__ A,
                              const float* __restrict__ W,
                              const float* __restrict__ b) {
    int i = blockIdx.x;
    int j = threadIdx.x;
    float acc = b[j];
    for (int k = 0; k < LD; k++) acc += A[i * LD + k] * W[k * H + j];
    g_xini[(NQ + i) * H + j] = acc;
}

// ---------------- edge prep (+ zero agg + zero colstats) ---------------------
__global__ void edge_prep_kernel(const int* __restrict__ ei,
                                 const int* __restrict__ ecs,
                                 const float* __restrict__ ewt,
                                 const float* __restrict__ Wem,
                                 const float* __restrict__ bem) {
    int i = blockIdx.x * blockDim.x + threadIdx.x;
    if (blockIdx.x == 0 && threadIdx.x < H)
        g_colstats2[threadIdx.x] = make_float2(0.f, 0.f);
    // zero g_agg (grid-stride float4)
    float4 z = make_float4(0.f, 0.f, 0.f, 0.f);
    int nthreads = gridDim.x * blockDim.x;
    for (long j = i; j < (long)NN * H / 4; j += nthreads)
        ((float4*)g_agg)[j] = z;
    if (i >= ESEE) return;
    int e = ecs[i];
    int s = ei[e];
    int d = ei[EE + e];
    g_src[i] = s;
    g_dst[i] = d;
    float v = ewt[e] * Wem[0] + bem[0];
    v = v > 0.f ? v : 0.01f * v;
    asm volatile("red.global.add.v2.f32 [%0], {%1, %2};"
                 :: "l"(&g_degew[d]), "f"(1.0f), "f"(v) : "memory");
}

// ---------------- scatter-add (raw rows) -------------------------------------
__global__ void __launch_bounds__(256) scatter_raw_kernel(const float* __restrict__ x,
                                                          float* __restrict__ outbuf) {
    int e = blockIdx.x * 8 + (threadIdx.x >> 5);
    int lane = threadIdx.x & 31;
    int s = g_src[e];
    int d = g_dst[e];
    float4 v = *(const float4*)&x[s * H + lane * 4];
    asm volatile("red.global.add.v4.f32 [%0], {%1, %2, %3, %4};"
                 :: "l"(&outbuf[d * H + lane * 4]),
                    "f"(v.x), "f"(v.y), "f"(v.z), "f"(v.w) : "memory");
}

// ---------------- scatter-add with inline BN + leaky relu --------------------
__global__ void __launch_bounds__(256) scatter_bn_kernel(const float* __restrict__ x,
                                                         float* __restrict__ outbuf,
                                                         const float* __restrict__ sc,
                                                         const float* __restrict__ sh) {
    int e = blockIdx.x * 8 + (threadIdx.x >> 5);
    int lane = threadIdx.x & 31;
    float4 s4 = *(const float4*)&sc[lane * 4];
    float4 h4 = *(const float4*)&sh[lane * 4];
    int s = g_src[e];
    int d = g_dst[e];
    float4 v = *(const float4*)&x[s * H + lane * 4];
    v.x = fmaf(v.x, s4.x, h4.x); v.x = v.x > 0.f ? v.x : 0.01f * v.x;
    v.y = fmaf(v.y, s4.y, h4.y); v.y = v.y > 0.f ? v.y : 0.01f * v.y;
    v.z = fmaf(v.z, s4.z, h4.z); v.z = v.z > 0.f ? v.z : 0.01f * v.z;
    v.w = fmaf(v.w, s4.w, h4.w); v.w = v.w > 0.f ? v.w : 0.01f * v.w;
    asm volatile("red.global.add.v4.f32 [%0], {%1, %2, %3, %4};"
                 :: "l"(&outbuf[d * H + lane * 4]),
                    "f"(v.x), "f"(v.y), "f"(v.z), "f"(v.w) : "memory");
}

// ---------------- BN stat finalize (+ self-zero for next layer) --------------
__global__ void finalize_kernel(const float* __restrict__ g,
                                const float* __restrict__ beta,
                                float* __restrict__ sc_out,
                                float* __restrict__ sh_out) {
    int j = threadIdx.x;
    float2 s = g_colstats2[j];
    float mu = s.x * (1.f / (float)NN);
    float var = s.y * (1.f / (float)NN) - mu * mu;
    float rstd = rsqrtf(var + BN_EPS);
    float sc = g[j] * rstd;
    sc_out[j] = sc;
    sh_out[j] = beta[j] - mu * sc;
    g_colstats2[j] = make_float2(0.f, 0.f);
}

// ---------------- edge prediction (BN2 inline) --------------------------------
__global__ void predict_kernel(const int* __restrict__ ei,
                               const int* __restrict__ em,
                               const float* __restrict__ x2raw,
                               const float* __restrict__ sc,
                               const float* __restrict__ sh,
                               float* __restrict__ out) {
    int warp = (blockIdx.x * blockDim.x + threadIdx.x) >> 5;
    int lane = threadIdx.x & 31;
    if (warp >= EPRED) return;
    float4 s2 = *(const float4*)&sc[lane * 4];
    float4 h2 = *(const float4*)&sh[lane * 4];
    int e = em[warp];
    int s = ei[e];
    int t = ei[EE + e];
    float4 a = *(const float4*)&g_xini[s * H + lane * 4];
    float4 b = *(const float4*)&x2raw[t * H + lane * 4];
    b.x = fmaf(b.x, s2.x, h2.x);
    b.y = fmaf(b.y, s2.y, h2.y);
    b.z = fmaf(b.z, s2.z, h2.z);
    b.w = fmaf(b.w, s2.w, h2.w);
    float d = a.x * b.x + a.y * b.y + a.z * b.z + a.w * b.w;
#pragma unroll
    for (int o = 16; o; o >>= 1) d += __shfl_xor_sync(0xffffffffu, d, o);
    if (lane == 0) out[warp] = 1.f / (1.f + expf(-d * (1.f / 128.f)));
}

// ---------------- launch -----------------------------------------------------
extern "C" void kernel_launch(void* const* d_in, const int* in_sizes, int n_in,
                              void* d_out, int out_size) {
    const float* qf  = (const float*)d_in[0];
    const float* lf  = (const float*)d_in[1];
    const int*   ei  = (const int*)d_in[2];
    const int*   em  = (const int*)d_in[3];
    const int*   ecs = (const int*)d_in[4];
    const float* ewt = (const float*)d_in[5];
    const float* Wq  = (const float*)d_in[6];
    const float* bq  = (const float*)d_in[7];
    const float* Wl  = (const float*)d_in[8];
    const float* bl  = (const float*)d_in[9];
    const float* Wem = (const float*)d_in[10];
    const float* bem = (const float*)d_in[11];
    const float* W1m = (const float*)d_in[12];
    const float* b1m = (const float*)d_in[13];
    const float* W1e = (const float*)d_in[14];
    const float* b1e = (const float*)d_in[15];
    const float* W2m = (const float*)d_in[16];
    const float* b2m = (const float*)d_in[17];
    const float* W2e = (const float*)d_in[18];
    const float* b2e = (const float*)d_in[19];
    const float* g1    = (const float*)d_in[20];
    const float* beta1 = (const float*)d_in[21];
    const float* g2    = (const float*)d_in[22];
    const float* beta2 = (const float*)d_in[23];
    float* out = (float*)d_out;

    void *p_agg, *p_xini, *p_x1, *p_degew;
    void *p_sc1, *p_sh1, *p_sc2, *p_sh2;
    void *p_w1hi, *p_w1lo, *p_w2hi, *p_w2lo;
    cudaGetSymbolAddress(&p_agg, g_agg);
    cudaGetSymbolAddress(&p_xini, g_xini);
    cudaGetSymbolAddress(&p_x1, g_x1);
    cudaGetSymbolAddress(&p_degew, g_degew);
    cudaGetSymbolAddress(&p_sc1, g_scale1);
    cudaGetSymbolAddress(&p_sh1, g_shift1);
    cudaGetSymbolAddress(&p_sc2, g_scale2);
    cudaGetSymbolAddress(&p_sh2, g_shift2);
    cudaGetSymbolAddress(&p_w1hi, g_w1hi);
    cudaGetSymbolAddress(&p_w1lo, g_w1lo);
    cudaGetSymbolAddress(&p_w2hi, g_w2hi);
    cudaGetSymbolAddress(&p_w2lo, g_w2lo);

    static int smem_set = 0;
    if (!smem_set) {
        cudaFuncSetAttribute(proj_q_mma, cudaFuncAttributeMaxDynamicSharedMemorySize,
                             SMEM_MMA);
        cudaFuncSetAttribute(layer_gemm_mma, cudaFuncAttributeMaxDynamicSharedMemorySize,
                             SMEM_MMA);
        smem_set = 1;
    }

    // launch order tuned so index 6 (ncu capture) = layer_gemm_mma L1
    cudaMemsetAsync(p_degew, 0, NN * sizeof(float2));                       // 0
    prep_all_kernel<<<(QD * H + 2 * H * H + 255) / 256, 256>>>(Wq, W1m, W2m); // 1
    proj_l_kernel<<<NL, H>>>(lf, Wl, bl);                                   // 2
    edge_prep_kernel<<<(ESEE + 255) / 256, 256>>>(ei, ecs, ewt, Wem, bem);  // 3
    proj_q_mma<<<GRID_TC, 256, SMEM_MMA>>>(qf, bq, (float*)p_xini);         // 4
    scatter_raw_kernel<<<ESEE / 8, 256>>>((const float*)p_xini, (float*)p_agg); // 5
    layer_gemm_mma<<<GRID_TC, 256, SMEM_MMA>>>(                             // 6 <- profiled
        (const float*)p_agg, (const __nv_bfloat16*)p_w1hi, (const __nv_bfloat16*)p_w1lo,
        b1m, b1e, W1e, (const float*)p_xini,
        nullptr, nullptr, 0, (float*)p_agg, (float*)p_x1);
    finalize_kernel<<<1, H>>>(g1, beta1, (float*)p_sc1, (float*)p_sh1);     // 7
    scatter_bn_kernel<<<ESEE / 8, 256>>>((const float*)p_agg, (float*)p_x1, // 8
                                         (const float*)p_sc1, (const float*)p_sh1);
    layer_gemm_mma<<<GRID_TC, 256, SMEM_MMA>>>(                             // 9
        (const float*)p_x1, (const __nv_bfloat16*)p_w2hi, (const __nv_bfloat16*)p_w2lo,
        b2m, b2e, W2e, (const float*)p_agg,
        (const float*)p_sc1, (const float*)p_sh1, 1, (float*)p_x1, nullptr);
    finalize_kernel<<<1, H>>>(g2, beta2, (float*)p_sc2, (float*)p_sh2);     // 10
    predict_kernel<<<EPRED / 8, 256>>>(ei, em, (const float*)p_x1,          // 11
                                       (const float*)p_sc2, (const float*)p_sh2, out);
}

// round 9
// speedup vs baseline: 2.7919x; 1.1494x over previous
#include <cuda_runtime.h>
#include <cuda_bf16.h>
#include <math.h>
#include <stdint.h>

#define NQ    100000
#define NL    32
#define NN    100032
#define QD    384
#define LD    1024
#define H     128
#define EE    1000000
#define ESEE  750000
#define EPRED 250000
#define BN_EPS 1e-5f
#define SCAN_B 391               // ceil(NN/256)

// mma tile config
#define BM 128
#define BK 32
#define GRID_TC 782
#define A_STRIDE_B 80
#define B_STRIDE_B 272
#define AHI_OFF 0
#define ALO_OFF 20480
#define BHI_OFF 40960
#define BLO_OFF 58368
#define SMEM_MMA 75776

// ---------------- scratch ------------------------------------------------
__device__ __align__(16) float g_xini[NN * H];
__device__ __align__(16) float g_agg [NN * H];
__device__ __align__(16) float g_x1  [NN * H];
__device__ int    g_src[ESEE];
__device__ int    g_dst[ESEE];
__device__ int    g_esrc[ESEE];          // dst-sorted src indices
__device__ int    g_off[NN + 1];
__device__ int    g_cursor[NN];
__device__ int    g_blk[SCAN_B];
__device__ __align__(8) float2 g_degew[NN];
__device__ __align__(8) float2 g_colstats2[H];
__device__ float g_scale1[H], g_shift1[H];
__device__ float g_scale2[H], g_shift2[H];
__device__ __align__(16) __nv_bfloat16 g_wqhi[QD * H], g_wqlo[QD * H];
__device__ __align__(16) __nv_bfloat16 g_w1hi[H * H],  g_w1lo[H * H];
__device__ __align__(16) __nv_bfloat16 g_w2hi[H * H],  g_w2lo[H * H];

// ---------------- ptx helpers ----------------------------------------------
__device__ __forceinline__ unsigned smem_u32(const void* p) {
    return (unsigned)__cvta_generic_to_shared(p);
}
__device__ __forceinline__ void cp16(unsigned dst, const void* src) {
    asm volatile("cp.async.ca.shared.global [%0], [%1], 16;" :: "r"(dst), "l"(src));
}
#define CP_COMMIT() asm volatile("cp.async.commit_group;")

#define LDSM_X4(r0, r1, r2, r3, addr) \
    asm volatile("ldmatrix.sync.aligned.m8n8.x4.shared.b16 {%0,%1,%2,%3}, [%4];" \
                 : "=r"(r0), "=r"(r1), "=r"(r2), "=r"(r3) : "r"(addr))
#define LDSM_X4T(r0, r1, r2, r3, addr) \
    asm volatile("ldmatrix.sync.aligned.m8n8.x4.trans.shared.b16 {%0,%1,%2,%3}, [%4];" \
                 : "=r"(r0), "=r"(r1), "=r"(r2), "=r"(r3) : "r"(addr))
#define MMA_BF16(c, a, b) \
    asm volatile("mma.sync.aligned.m16n8k16.row.col.f32.bf16.bf16.f32 " \
                 "{%0,%1,%2,%3}, {%4,%5,%6,%7}, {%8,%9}, {%0,%1,%2,%3};" \
                 : "+f"((c)[0]), "+f"((c)[1]), "+f"((c)[2]), "+f"((c)[3]) \
                 : "r"((a)[0]), "r"((a)[1]), "r"((a)[2]), "r"((a)[3]), \
                   "r"((b)[0]), "r"((b)[1]))

__device__ __forceinline__ void split_store(char* smg, int off_hi, int off_lo,
                                            int row, int c4, float4 v) {
    __nv_bfloat16 h0 = __float2bfloat16(v.x);
    __nv_bfloat16 h1 = __float2bfloat16(v.y);
    __nv_bfloat16 h2 = __float2bfloat16(v.z);
    __nv_bfloat16 h3 = __float2bfloat16(v.w);
    __nv_bfloat16 l0 = __float2bfloat16(v.x - __bfloat162float(h0));
    __nv_bfloat16 l1 = __float2bfloat16(v.y - __bfloat162float(h1));
    __nv_bfloat16 l2 = __float2bfloat16(v.z - __bfloat162float(h2));
    __nv_bfloat16 l3 = __float2bfloat16(v.w - __bfloat162float(h3));
    uint2 hp, lp;
    hp.x = ((uint32_t)__bfloat16_as_ushort(h1) << 16) | __bfloat16_as_ushort(h0);
    hp.y = ((uint32_t)__bfloat16_as_ushort(h3) << 16) | __bfloat16_as_ushort(h2);
    lp.x = ((uint32_t)__bfloat16_as_ushort(l1) << 16) | __bfloat16_as_ushort(l0);
    lp.y = ((uint32_t)__bfloat16_as_ushort(l3) << 16) | __bfloat16_as_ushort(l2);
    *(uint2*)(smg + off_hi + row * A_STRIDE_B + c4 * 8) = hp;
    *(uint2*)(smg + off_lo + row * A_STRIDE_B + c4 * 8) = lp;
}

// ---------------- W prep ------------------------------------------------------
__global__ void prep_all_kernel(const float* __restrict__ Wq,
                                const float* __restrict__ W1,
                                const float* __restrict__ W2) {
    int idx = blockIdx.x * blockDim.x + threadIdx.x;
    const int NQW = QD * H, NW = H * H;
    float w;
    __nv_bfloat16 *dhi, *dlo;
    int j;
    if (idx < NQW)                { w = Wq[idx]; dhi = g_wqhi; dlo = g_wqlo; j = idx; }
    else if (idx < NQW + NW)      { j = idx - NQW; w = W1[j]; dhi = g_w1hi; dlo = g_w1lo; }
    else if (idx < NQW + 2 * NW)  { j = idx - NQW - NW; w = W2[j]; dhi = g_w2hi; dlo = g_w2lo; }
    else return;
    __nv_bfloat16 hi = __float2bfloat16(w);
    dhi[j] = hi;
    dlo[j] = __float2bfloat16(w - __bfloat162float(hi));
}

// ---------------- edge prep (+ zero colstats) ---------------------------------
__global__ void edge_prep_kernel(const int* __restrict__ ei,
                                 const int* __restrict__ ecs,
                                 const float* __restrict__ ewt,
                                 const float* __restrict__ Wem,
                                 const float* __restrict__ bem) {
    int i = blockIdx.x * blockDim.x + threadIdx.x;
    if (blockIdx.x == 0 && threadIdx.x < H)
        g_colstats2[threadIdx.x] = make_float2(0.f, 0.f);
    if (i >= ESEE) return;
    int e = ecs[i];
    int s = ei[e];
    int d = ei[EE + e];
    g_src[i] = s;
    g_dst[i] = d;
    float v = ewt[e] * Wem[0] + bem[0];
    v = v > 0.f ? v : 0.01f * v;
    asm volatile("red.global.add.v2.f32 [%0], {%1, %2};"
                 :: "l"(&g_degew[d]), "f"(1.0f), "f"(v) : "memory");
}

// ---------------- counting-sort scan trio --------------------------------------
__global__ void scan1_kernel() {
    __shared__ int red[256];
    int t = threadIdx.x;
    int i = blockIdx.x * 256 + t;
    int c = (i < NN) ? (int)g_degew[i].x : 0;
    red[t] = c;
    __syncthreads();
#pragma unroll
    for (int o = 128; o > 0; o >>= 1) {
        if (t < o) red[t] += red[t + o];
        __syncthreads();
    }
    if (t == 0) g_blk[blockIdx.x] = red[0];
}

__global__ void scan2_kernel() {
    __shared__ int s[512];
    int t = threadIdx.x;
    int c = (t < SCAN_B) ? g_blk[t] : 0;
    s[t] = c;
    __syncthreads();
    for (int o = 1; o < 512; o <<= 1) {
        int v = (t >= o) ? s[t - o] : 0;
        __syncthreads();
        s[t] += v;
        __syncthreads();
    }
    if (t < SCAN_B) g_blk[t] = s[t] - c;  // exclusive
}

__global__ void scan3_kernel() {
    __shared__ int s[256];
    int t = threadIdx.x;
    int i = blockIdx.x * 256 + t;
    int c = (i < NN) ? (int)g_degew[i].x : 0;
    s[t] = c;
    __syncthreads();
    for (int o = 1; o < 256; o <<= 1) {
        int v = (t >= o) ? s[t - o] : 0;
        __syncthreads();
        s[t] += v;
        __syncthreads();
    }
    if (i < NN) {
        int off = g_blk[blockIdx.x] + s[t] - c;
        g_off[i] = off;
        g_cursor[i] = off;
    }
    if (i == 0) g_off[NN] = ESEE;
}

__global__ void placement_kernel() {
    int i = blockIdx.x * blockDim.x + threadIdx.x;
    if (i >= ESEE) return;
    int d = g_dst[i];
    int pos = atomicAdd(&g_cursor[d], 1);
    g_esrc[pos] = g_src[i];
}

// ---------------- gather aggregation (no atomics, no pre-zero) ----------------
__global__ void __launch_bounds__(256) gather_kernel(const float* __restrict__ x,
                                                     float* __restrict__ outbuf,
                                                     const float* __restrict__ sc,
                                                     const float* __restrict__ sh,
                                                     int bn) {
    int wid = threadIdx.x >> 5;
    int lane = threadIdx.x & 31;
    int node = blockIdx.x * 8 + wid;
    if (node >= NN) return;
    int o0 = g_off[node];
    int o1 = g_off[node + 1];
    float4 s4 = make_float4(1.f, 1.f, 1.f, 1.f);
    float4 h4 = make_float4(0.f, 0.f, 0.f, 0.f);
    if (bn) {
        s4 = *(const float4*)&sc[lane * 4];
        h4 = *(const float4*)&sh[lane * 4];
    }
    float4 a0 = make_float4(0.f, 0.f, 0.f, 0.f);
    float4 a1 = make_float4(0.f, 0.f, 0.f, 0.f);
    int e = o0;
    for (; e + 2 <= o1; e += 2) {
        int s0 = g_esrc[e], s1 = g_esrc[e + 1];
        float4 v0 = *(const float4*)&x[(long)s0 * H + lane * 4];
        float4 v1 = *(const float4*)&x[(long)s1 * H + lane * 4];
        if (bn) {
            v0.x = fmaf(v0.x, s4.x, h4.x); v0.x = v0.x > 0.f ? v0.x : 0.01f * v0.x;
            v0.y = fmaf(v0.y, s4.y, h4.y); v0.y = v0.y > 0.f ? v0.y : 0.01f * v0.y;
            v0.z = fmaf(v0.z, s4.z, h4.z); v0.z = v0.z > 0.f ? v0.z : 0.01f * v0.z;
            v0.w = fmaf(v0.w, s4.w, h4.w); v0.w = v0.w > 0.f ? v0.w : 0.01f * v0.w;
            v1.x = fmaf(v1.x, s4.x, h4.x); v1.x = v1.x > 0.f ? v1.x : 0.01f * v1.x;
            v1.y = fmaf(v1.y, s4.y, h4.y); v1.y = v1.y > 0.f ? v1.y : 0.01f * v1.y;
            v1.z = fmaf(v1.z, s4.z, h4.z); v1.z = v1.z > 0.f ? v1.z : 0.01f * v1.z;
            v1.w = fmaf(v1.w, s4.w, h4.w); v1.w = v1.w > 0.f ? v1.w : 0.01f * v1.w;
        }
        a0.x += v0.x; a0.y += v0.y; a0.z += v0.z; a0.w += v0.w;
        a1.x += v1.x; a1.y += v1.y; a1.z += v1.z; a1.w += v1.w;
    }
    if (e < o1) {
        int s0 = g_esrc[e];
        float4 v0 = *(const float4*)&x[(long)s0 * H + lane * 4];
        if (bn) {
            v0.x = fmaf(v0.x, s4.x, h4.x); v0.x = v0.x > 0.f ? v0.x : 0.01f * v0.x;
            v0.y = fmaf(v0.y, s4.y, h4.y); v0.y = v0.y > 0.f ? v0.y : 0.01f * v0.y;
            v0.z = fmaf(v0.z, s4.z, h4.z); v0.z = v0.z > 0.f ? v0.z : 0.01f * v0.z;
            v0.w = fmaf(v0.w, s4.w, h4.w); v0.w = v0.w > 0.f ? v0.w : 0.01f * v0.w;
        }
        a0.x += v0.x; a0.y += v0.y; a0.z += v0.z; a0.w += v0.w;
    }
    a0.x += a1.x; a0.y += a1.y; a0.z += a1.z; a0.w += a1.w;
    *(float4*)&outbuf[(long)node * H + lane * 4] = a0;
}

// ---------------- proj_q via mma.sync bf16x3 ----------------------------------
__global__ void __launch_bounds__(256, 1) proj_q_mma(const float* __restrict__ A,
                                                     const float* __restrict__ bias,
                                                     float* __restrict__ out) {
    extern __shared__ char sm[];
    uint32_t sb = smem_u32(sm);
    char* smg = sm;
    int tid = threadIdx.x;
    int wid = tid >> 5;
    int lane = tid & 31;
    int wm = wid & 3;
    int wn = wid >> 2;
    int row0 = blockIdx.x * BM;

    float acc[2][8][4];
#pragma unroll
    for (int mt = 0; mt < 2; mt++)
#pragma unroll
        for (int nt = 0; nt < 8; nt++)
#pragma unroll
            for (int j = 0; j < 4; j++) acc[mt][nt][j] = 0.f;

    int af_row[4], af_c4[4];
#pragma unroll
    for (int i = 0; i < 4; i++) {
        int f = tid + i * 256;
        af_row[i] = f >> 3;
        af_c4[i] = f & 7;
    }

    float4 av[4];
#pragma unroll
    for (int i = 0; i < 4; i++) {
        int grow = row0 + af_row[i];
        if (grow >= NQ) grow = 0;
        av[i] = *(const float4*)&A[(long)grow * QD + af_c4[i] * 4];
    }
#pragma unroll
    for (int i = 0; i < 2; i++) {
        int seg = tid + i * 256;
        int br = seg >> 4, c16 = seg & 15;
        cp16(sb + BHI_OFF + br * B_STRIDE_B + c16 * 16, g_wqhi + br * H + c16 * 8);
        cp16(sb + BLO_OFF + br * B_STRIDE_B + c16 * 16, g_wqlo + br * H + c16 * 8);
    }
    CP_COMMIT();
#pragma unroll
    for (int i = 0; i < 4; i++)
        split_store(smg, AHI_OFF, ALO_OFF, af_row[i], af_c4[i], av[i]);

    const int TST = QD / BK;  // 12
    for (int t = 0; t < TST; t++) {
        int buf = t & 1;
        int have_next = (t + 1 < TST);
        if (have_next) {
            int k0 = (t + 1) * BK;
            int nb = buf ^ 1;
#pragma unroll
            for (int i = 0; i < 4; i++) {
                int grow = row0 + af_row[i];
                if (grow >= NQ) grow = 0;
                av[i] = *(const float4*)&A[(long)grow * QD + k0 + af_c4[i] * 4];
            }
#pragma unroll
            for (int i = 0; i < 2; i++) {
                int seg = tid + i * 256;
                int br = seg >> 4, c16 = seg & 15;
                cp16(sb + BHI_OFF + nb * 8704 + br * B_STRIDE_B + c16 * 16,
                     g_wqhi + (k0 + br) * H + c16 * 8);
                cp16(sb + BLO_OFF + nb * 8704 + br * B_STRIDE_B + c16 * 16,
                     g_wqlo + (k0 + br) * H + c16 * 8);
            }
            CP_COMMIT();
            asm volatile("cp.async.wait_group 1;");
        } else {
            asm volatile("cp.async.wait_group 0;");
        }
        __syncthreads();

        uint32_t abase_hi = sb + AHI_OFF + buf * 10240;
        uint32_t abase_lo = sb + ALO_OFF + buf * 10240;
        uint32_t bbase_hi = sb + BHI_OFF + buf * 8704;
        uint32_t bbase_lo = sb + BLO_OFF + buf * 8704;
#pragma unroll
        for (int ks = 0; ks < 2; ks++) {
            uint32_t ah[2][4], al[2][4], bh[8][2], bl[8][2];
#pragma unroll
            for (int mt = 0; mt < 2; mt++) {
                uint32_t roff = (uint32_t)((wm * 32 + mt * 16 + (lane & 15)) * A_STRIDE_B
                                           + ks * 32 + (lane >> 4) * 16);
                LDSM_X4(ah[mt][0], ah[mt][1], ah[mt][2], ah[mt][3], abase_hi + roff);
                LDSM_X4(al[mt][0], al[mt][1], al[mt][2], al[mt][3], abase_lo + roff);
            }
#pragma unroll
            for (int np = 0; np < 4; np++) {
                uint32_t boff = (uint32_t)((ks * 16 + (lane & 15)) * B_STRIDE_B
                                           + (wn * 64 + np * 16 + (lane >> 4) * 8) * 2);
                LDSM_X4T(bh[np * 2][0], bh[np * 2][1], bh[np * 2 + 1][0], bh[np * 2 + 1][1],
                         bbase_hi + boff);
                LDSM_X4T(bl[np * 2][0], bl[np * 2][1], bl[np * 2 + 1][0], bl[np * 2 + 1][1],
                         bbase_lo + boff);
            }
#pragma unroll
            for (int mt = 0; mt < 2; mt++)
#pragma unroll
                for (int nt = 0; nt < 8; nt++) {
                    MMA_BF16(acc[mt][nt], ah[mt], bh[nt]);
                    MMA_BF16(acc[mt][nt], al[mt], bh[nt]);
                    MMA_BF16(acc[mt][nt], ah[mt], bl[nt]);
                }
        }
        __syncthreads();

        if (have_next) {
            int nb = buf ^ 1;
#pragma unroll
            for (int i = 0; i < 4; i++)
                split_store(smg, AHI_OFF + nb * 10240, ALO_OFF + nb * 10240,
                            af_row[i], af_c4[i], av[i]);
        }
    }

#pragma unroll
    for (int mt = 0; mt < 2; mt++) {
        int m0r = row0 + wm * 32 + mt * 16 + (lane >> 2);
        int m1r = m0r + 8;
#pragma unroll
        for (int nt = 0; nt < 8; nt++) {
            int n = wn * 64 + nt * 8 + (lane & 3) * 2;
            float2 bv = *(const float2*)&bias[n];
            if (m0r < NQ) {
                float2 o = make_float2(acc[mt][nt][0] + bv.x, acc[mt][nt][1] + bv.y);
                *(float2*)&out[(long)m0r * H + n] = o;
            }
            if (m1r < NQ) {
                float2 o = make_float2(acc[mt][nt][2] + bv.x, acc[mt][nt][3] + bv.y);
                *(float2*)&out[(long)m1r * H + n] = o;
            }
        }
    }
}

// ---------------- layer GEMM via mma.sync bf16x3 + fused epilogue ------------
__global__ void __launch_bounds__(256, 1) layer_gemm_mma(
        const float* __restrict__ Ain,
        const __nv_bfloat16* __restrict__ Whi,
        const __nv_bfloat16* __restrict__ Wlo,
        const float* __restrict__ bm, const float* __restrict__ be,
        const float* __restrict__ We,
        const float* __restrict__ xprev,
        const float* __restrict__ psc, const float* __restrict__ psh,
        int prev_bn,
        float* __restrict__ out) {
    extern __shared__ char sm[];
    uint32_t sb = smem_u32(sm);
    char* smg = sm;
    int tid = threadIdx.x;
    int wid = tid >> 5;
    int lane = tid & 31;
    int wm = wid & 3;
    int wn = wid >> 2;
    int row0 = blockIdx.x * BM;

    float acc[2][8][4];
#pragma unroll
    for (int mt = 0; mt < 2; mt++)
#pragma unroll
        for (int nt = 0; nt < 8; nt++)
#pragma unroll
            for (int j = 0; j < 4; j++) acc[mt][nt][j] = 0.f;

    int af_row[4], af_c4[4];
#pragma unroll
    for (int i = 0; i < 4; i++) {
        int f = tid + i * 256;
        af_row[i] = f >> 3;
        af_c4[i] = f & 7;
    }

    float4 av[4];
#pragma unroll
    for (int i = 0; i < 4; i++) {
        int grow = row0 + af_row[i];
        if (grow >= NN) grow = 0;
        av[i] = *(const float4*)&Ain[(long)grow * H + af_c4[i] * 4];
    }
#pragma unroll
    for (int i = 0; i < 2; i++) {
        int seg = tid + i * 256;
        int br = seg >> 4, c16 = seg & 15;
        cp16(sb + BHI_OFF + br * B_STRIDE_B + c16 * 16, Whi + br * H + c16 * 8);
        cp16(sb + BLO_OFF + br * B_STRIDE_B + c16 * 16, Wlo + br * H + c16 * 8);
    }
    CP_COMMIT();
#pragma unroll
    for (int i = 0; i < 4; i++)
        split_store(smg, AHI_OFF, ALO_OFF, af_row[i], af_c4[i], av[i]);

    const int TST = H / BK;  // 4
    for (int t = 0; t < TST; t++) {
        int buf = t & 1;
        int have_next = (t + 1 < TST);
        if (have_next) {
            int k0 = (t + 1) * BK;
            int nb = buf ^ 1;
#pragma unroll
            for (int i = 0; i < 4; i++) {
                int grow = row0 + af_row[i];
                if (grow >= NN) grow = 0;
                av[i] = *(const float4*)&Ain[(long)grow * H + k0 + af_c4[i] * 4];
            }
#pragma unroll
            for (int i = 0; i < 2; i++) {
                int seg = tid + i * 256;
                int br = seg >> 4, c16 = seg & 15;
                cp16(sb + BHI_OFF + nb * 8704 + br * B_STRIDE_B + c16 * 16,
                     Whi + (k0 + br) * H + c16 * 8);
                cp16(sb + BLO_OFF + nb * 8704 + br * B_STRIDE_B + c16 * 16,
                     Wlo + (k0 + br) * H + c16 * 8);
            }
            CP_COMMIT();
            asm volatile("cp.async.wait_group 1;");
        } else {
            asm volatile("cp.async.wait_group 0;");
        }
        __syncthreads();

        uint32_t abase_hi = sb + AHI_OFF + buf * 10240;
        uint32_t abase_lo = sb + ALO_OFF + buf * 10240;
        uint32_t bbase_hi = sb + BHI_OFF + buf * 8704;
        uint32_t bbase_lo = sb + BLO_OFF + buf * 8704;
#pragma unroll
        for (int ks = 0; ks < 2; ks++) {
            uint32_t ah[2][4], al[2][4], bh[8][2], bl[8][2];
#pragma unroll
            for (int mt = 0; mt < 2; mt++) {
                uint32_t roff = (uint32_t)((wm * 32 + mt * 16 + (lane & 15)) * A_STRIDE_B
                                           + ks * 32 + (lane >> 4) * 16);
                LDSM_X4(ah[mt][0], ah[mt][1], ah[mt][2], ah[mt][3], abase_hi + roff);
                LDSM_X4(al[mt][0], al[mt][1], al[mt][2], al[mt][3], abase_lo + roff);
            }
#pragma unroll
            for (int np = 0; np < 4; np++) {
                uint32_t boff = (uint32_t)((ks * 16 + (lane & 15)) * B_STRIDE_B
                                           + (wn * 64 + np * 16 + (lane >> 4) * 8) * 2);
                LDSM_X4T(bh[np * 2][0], bh[np * 2][1], bh[np * 2 + 1][0], bh[np * 2 + 1][1],
                         bbase_hi + boff);
                LDSM_X4T(bl[np * 2][0], bl[np * 2][1], bl[np * 2 + 1][0], bl[np * 2 + 1][1],
                         bbase_lo + boff);
            }
#pragma unroll
            for (int mt = 0; mt < 2; mt++)
#pragma unroll
                for (int nt = 0; nt < 8; nt++) {
                    MMA_BF16(acc[mt][nt], ah[mt], bh[nt]);
                    MMA_BF16(acc[mt][nt], al[mt], bh[nt]);
                    MMA_BF16(acc[mt][nt], ah[mt], bl[nt]);
                }
        }
        __syncthreads();

        if (have_next) {
            int nb = buf ^ 1;
#pragma unroll
            for (int i = 0; i < 4; i++)
                split_store(smg, AHI_OFF + nb * 10240, ALO_OFF + nb * 10240,
                            af_row[i], af_c4[i], av[i]);
        }
    }

    // ---- fused epilogue: deg/sumew/residual + BN column stats ----
    int lq = lane & 3;
    int lr = lane >> 2;
    float2 ds[2][2];
    bool rv[2][2];
#pragma unroll
    for (int mt = 0; mt < 2; mt++)
#pragma unroll
        for (int hf = 0; hf < 2; hf++) {
            int row = row0 + wm * 32 + mt * 16 + hf * 8 + lr;
            rv[mt][hf] = (row < NN);
            ds[mt][hf] = rv[mt][hf] ? g_degew[row] : make_float2(0.f, 0.f);
        }

#pragma unroll
    for (int nt = 0; nt < 8; nt++) {
        int n = wn * 64 + nt * 8 + lq * 2;
        float2 cb2 = make_float2(bm[n] + be[n], bm[n + 1] + be[n + 1]);
        float2 we2 = *(const float2*)&We[n];
        float2 sc2 = make_float2(0.f, 0.f), sh2 = make_float2(0.f, 0.f);
        if (prev_bn) {
            sc2 = make_float2(psc[n], psc[n + 1]);
            sh2 = make_float2(psh[n], psh[n + 1]);
        }
        float cs0 = 0.f, cs1 = 0.f, cq0 = 0.f, cq1 = 0.f;
#pragma unroll
        for (int mt = 0; mt < 2; mt++)
#pragma unroll
            for (int hf = 0; hf < 2; hf++) {
                if (rv[mt][hf]) {
                    int row = row0 + wm * 32 + mt * 16 + hf * 8 + lr;
                    float2 xp = *(const float2*)&xprev[(long)row * H + n];
                    if (prev_bn) {
                        float u0 = fmaf(xp.x, sc2.x, sh2.x);
                        float u1 = fmaf(xp.y, sc2.y, sh2.y);
                        xp.x = u0 > 0.f ? u0 : 0.01f * u0;
                        xp.y = u1 > 0.f ? u1 : 0.01f * u1;
                    }
                    float2 dd = ds[mt][hf];
                    float v0 = acc[mt][nt][hf * 2 + 0] + dd.x * cb2.x + dd.y * we2.x + xp.x;
                    float v1 = acc[mt][nt][hf * 2 + 1] + dd.x * cb2.y + dd.y * we2.y + xp.y;
                    *(float2*)&out[(long)row * H + n] = make_float2(v0, v1);
                    cs0 += v0; cq0 += v0 * v0;
                    cs1 += v1; cq1 += v1 * v1;
                }
            }
#pragma unroll
        for (int off = 4; off <= 16; off <<= 1) {
            cs0 += __shfl_xor_sync(0xffffffffu, cs0, off);
            cq0 += __shfl_xor_sync(0xffffffffu, cq0, off);
            cs1 += __shfl_xor_sync(0xffffffffu, cs1, off);
            cq1 += __shfl_xor_sync(0xffffffffu, cq1, off);
        }
        if (lr == 0) {
            asm volatile("red.global.add.v2.f32 [%0], {%1, %2};"
                         :: "l"(&g_colstats2[n]), "f"(cs0), "f"(cq0) : "memory");
            asm volatile("red.global.add.v2.f32 [%0], {%1, %2};"
                         :: "l"(&g_colstats2[n + 1]), "f"(cs1), "f"(cq1) : "memory");
        }
    }
}

// ---------------- llm projection ----------------------------------------------
__global__ void proj_l_kernel(const float* __restrict__ A,
                              const float* __restrict__ W,
                              const float* __restrict__ b) {
    int i = blockIdx.x;
    int j = threadIdx.x;
    float acc = b[j];
    for (int k = 0; k < LD; k++) acc += A[i * LD + k] * W[k * H + j];
    g_xini[(NQ + i) * H + j] = acc;
}

// ---------------- BN stat finalize (+ self-zero) -------------------------------
__global__ void finalize_kernel(const float* __restrict__ g,
                                const float* __restrict__ beta,
                                float* __restrict__ sc_out,
                                float* __restrict__ sh_out) {
    int j = threadIdx.x;
    float2 s = g_colstats2[j];
    float mu = s.x * (1.f / (float)NN);
    float var = s.y * (1.f / (float)NN) - mu * mu;
    float rstd = rsqrtf(var + BN_EPS);
    float sc = g[j] * rstd;
    sc_out[j] = sc;
    sh_out[j] = beta[j] - mu * sc;
    g_colstats2[j] = make_float2(0.f, 0.f);
}

// ---------------- edge prediction (BN2 inline) ----------------------------------
__global__ void predict_kernel(const int* __restrict__ ei,
                               const int* __restrict__ em,
                               const float* __restrict__ x2raw,
                               const float* __restrict__ sc,
                               const float* __restrict__ sh,
                               float* __restrict__ out) {
    int warp = (blockIdx.x * blockDim.x + threadIdx.x) >> 5;
    int lane = threadIdx.x & 31;
    if (warp >= EPRED) return;
    float4 s2 = *(const float4*)&sc[lane * 4];
    float4 h2 = *(const float4*)&sh[lane * 4];
    int e = em[warp];
    int s = ei[e];
    int t = ei[EE + e];
    float4 a = *(const float4*)&g_xini[s * H + lane * 4];
    float4 b = *(const float4*)&x2raw[t * H + lane * 4];
    b.x = fmaf(b.x, s2.x, h2.x);
    b.y = fmaf(b.y, s2.y, h2.y);
    b.z = fmaf(b.z, s2.z, h2.z);
    b.w = fmaf(b.w, s2.w, h2.w);
    float d = a.x * b.x + a.y * b.y + a.z * b.z + a.w * b.w;
#pragma unroll
    for (int o = 16; o; o >>= 1) d += __shfl_xor_sync(0xffffffffu, d, o);
    if (lane == 0) out[warp] = 1.f / (1.f + expf(-d * (1.f / 128.f)));
}

// ---------------- launch -----------------------------------------------------
extern "C" void kernel_launch(void* const* d_in, const int* in_sizes, int n_in,
                              void* d_out, int out_size) {
    const float* qf  = (const float*)d_in[0];
    const float* lf  = (const float*)d_in[1];
    const int*   ei  = (const int*)d_in[2];
    const int*   em  = (const int*)d_in[3];
    const int*   ecs = (const int*)d_in[4];
    const float* ewt = (const float*)d_in[5];
    const float* Wq  = (const float*)d_in[6];
    const float* bq  = (const float*)d_in[7];
    const float* Wl  = (const float*)d_in[8];
    const float* bl  = (const float*)d_in[9];
    const float* Wem = (const float*)d_in[10];
    const float* bem = (const float*)d_in[11];
    const float* W1m = (const float*)d_in[12];
    const float* b1m = (const float*)d_in[13];
    const float* W1e = (const float*)d_in[14];
    const float* b1e = (const float*)d_in[15];
    const float* W2m = (const float*)d_in[16];
    const float* b2m = (const float*)d_in[17];
    const float* W2e = (const float*)d_in[18];
    const float* b2e = (const float*)d_in[19];
    const float* g1    = (const float*)d_in[20];
    const float* beta1 = (const float*)d_in[21];
    const float* g2    = (const float*)d_in[22];
    const float* beta2 = (const float*)d_in[23];
    float* out = (float*)d_out;

    void *p_agg, *p_xini, *p_x1, *p_degew;
    void *p_sc1, *p_sh1, *p_sc2, *p_sh2;
    void *p_w1hi, *p_w1lo, *p_w2hi, *p_w2lo;
    cudaGetSymbolAddress(&p_agg, g_agg);
    cudaGetSymbolAddress(&p_xini, g_xini);
    cudaGetSymbolAddress(&p_x1, g_x1);
    cudaGetSymbolAddress(&p_degew, g_degew);
    cudaGetSymbolAddress(&p_sc1, g_scale1);
    cudaGetSymbolAddress(&p_sh1, g_shift1);
    cudaGetSymbolAddress(&p_sc2, g_scale2);
    cudaGetSymbolAddress(&p_sh2, g_shift2);
    cudaGetSymbolAddress(&p_w1hi, g_w1hi);
    cudaGetSymbolAddress(&p_w1lo, g_w1lo);
    cudaGetSymbolAddress(&p_w2hi, g_w2hi);
    cudaGetSymbolAddress(&p_w2lo, g_w2lo);

    static int smem_set = 0;
    if (!smem_set) {
        cudaFuncSetAttribute(proj_q_mma, cudaFuncAttributeMaxDynamicSharedMemorySize,
                             SMEM_MMA);
        cudaFuncSetAttribute(layer_gemm_mma, cudaFuncAttributeMaxDynamicSharedMemorySize,
                             SMEM_MMA);
        smem_set = 1;
    }

    cudaMemsetAsync(p_degew, 0, NN * sizeof(float2));                       // 0
    prep_all_kernel<<<(QD * H + 2 * H * H + 255) / 256, 256>>>(Wq, W1m, W2m); // 1
    edge_prep_kernel<<<(ESEE + 255) / 256, 256>>>(ei, ecs, ewt, Wem, bem);  // 2
    scan1_kernel<<<SCAN_B, 256>>>();                                        // 3
    scan2_kernel<<<1, 512>>>();                                             // 4
    scan3_kernel<<<SCAN_B, 256>>>();                                        // 5
    placement_kernel<<<(ESEE + 255) / 256, 256>>>();                        // 6 <- profiled
    proj_l_kernel<<<NL, H>>>(lf, Wl, bl);                                   // 7
    proj_q_mma<<<GRID_TC, 256, SMEM_MMA>>>(qf, bq, (float*)p_xini);         // 8

    // ---- layer 1 ----
    gather_kernel<<<(NN + 7) / 8, 256>>>((const float*)p_xini, (float*)p_agg,
                                         nullptr, nullptr, 0);              // 9
    layer_gemm_mma<<<GRID_TC, 256, SMEM_MMA>>>(                             // 10
        (const float*)p_agg, (const __nv_bfloat16*)p_w1hi, (const __nv_bfloat16*)p_w1lo,
        b1m, b1e, W1e, (const float*)p_xini,
        nullptr, nullptr, 0, (float*)p_agg);
    finalize_kernel<<<1, H>>>(g1, beta1, (float*)p_sc1, (float*)p_sh1);     // 11

    // ---- layer 2 ----
    gather_kernel<<<(NN + 7) / 8, 256>>>((const float*)p_agg, (float*)p_x1,
                                         (const float*)p_sc1, (const float*)p_sh1, 1); // 12
    layer_gemm_mma<<<GRID_TC, 256, SMEM_MMA>>>(                             // 13
        (const float*)p_x1, (const __nv_bfloat16*)p_w2hi, (const __nv_bfloat16*)p_w2lo,
        b2m, b2e, W2e, (const float*)p_agg,
        (const float*)p_sc1, (const float*)p_sh1, 1, (float*)p_x1);
    finalize_kernel<<<1, H>>>(g2, beta2, (float*)p_sc2, (float*)p_sh2);     // 14
    predict_kernel<<<EPRED / 8, 256>>>(ei, em, (const float*)p_x1,          // 15
                                       (const float*)p_sc2, (const float*)p_sh2, out);
}